// round 14
// baseline (speedup 1.0000x reference)
#include <cuda_runtime.h>
#include <cuda_bf16.h>
#include <cstdint>

// ---------------- problem constants ----------------
constexpr int kB      = 128;
constexpr int kSeq    = 252;
constexpr int kWin    = 96;
constexpr int kLeads  = 12;
constexpr int kS      = 264;   // kSeq + kLeads
constexpr int kE      = 128;
constexpr int kH      = 8;
constexpr int kD      = 16;    // kE / kH
constexpr int kFF     = 512;
constexpr int kLayers = 12;
constexpr int kM      = kB * kS;   // 33792 tokens

// pair-widths (K/2) for packed bf16 hi/lo activations
constexpr int EP  = kE / 2;    // 64
constexpr int QP  = 192;       // 384/2
constexpr int FP  = kFF / 2;   // 256

// ---------------- scratch (device globals; no allocation allowed) ------------
__device__ float g_h   [kM * kE];   // residual stream (fp32)
__device__ float g_proj[kM * kE];   // O-proj / FFN2 fp32 outputs
__device__ uint32_t g_hh  [kM * EP],  g_hl  [kM * EP];
__device__ uint32_t g_qkvh[kM * QP],  g_qkvl[kM * QP];
__device__ uint32_t g_atth[kM * EP],  g_attl[kM * EP];
__device__ uint32_t g_ff1h[kM * FP],  g_ff1l[kM * FP];
__device__ uint32_t g_wqkvh[kLayers * 384 * EP], g_wqkvl[kLayers * 384 * EP];
__device__ uint32_t g_woh  [kLayers * kE  * EP], g_wol  [kLayers * kE  * EP];
__device__ uint32_t g_w1h  [kLayers * kFF * EP], g_w1l  [kLayers * kFF * EP];
__device__ uint32_t g_w2h  [kLayers * kE  * FP], g_w2l  [kLayers * kE  * FP];

// split sizes (pairs)
constexpr int NW_QKV = kLayers * 384 * EP;
constexpr int NW_O   = kLayers * kE  * EP;
constexpr int NW_1   = kLayers * kFF * EP;
constexpr int NW_2   = kLayers * kE  * FP;
constexpr int NW_TOT = NW_QKV + NW_O + NW_1 + NW_2;

// ---------------- bf16 split helpers ----------------
__device__ __forceinline__ float bhi(float x) {
    return __bfloat162float(__float2bfloat16(x));
}
__device__ __forceinline__ uint32_t packbf(float a, float b) {
    __nv_bfloat162 t;
    t.x = __float2bfloat16(a);
    t.y = __float2bfloat16(b);
    return *reinterpret_cast<uint32_t*>(&t);
}
__device__ __forceinline__ void split2(float a, float b, uint32_t& h, uint32_t& l) {
    float ha = bhi(a), hb = bhi(b);
    h = packbf(a, b);
    l = packbf(a - ha, b - hb);
}

#define MMA_BF16(d, a, b0, b1)                                                \
    asm volatile("mma.sync.aligned.m16n8k16.row.col.f32.bf16.bf16.f32 "       \
                 "{%0,%1,%2,%3}, {%4,%5,%6,%7}, {%8,%9}, {%0,%1,%2,%3};"      \
                 : "+f"(d[0]), "+f"(d[1]), "+f"(d[2]), "+f"(d[3])             \
                 : "r"(a[0]), "r"(a[1]), "r"(a[2]), "r"(a[3]),                \
                   "r"(b0), "r"(b1))

#define MMA_BF16_K8(d, a0, a1, b0)                                            \
    asm volatile("mma.sync.aligned.m16n8k8.row.col.f32.bf16.bf16.f32 "        \
                 "{%0,%1,%2,%3}, {%4,%5}, {%6}, {%0,%1,%2,%3};"               \
                 : "+f"(d[0]), "+f"(d[1]), "+f"(d[2]), "+f"(d[3])             \
                 : "r"(a0), "r"(a1), "r"(b0))

#define LDSM_X4(r0, r1, r2, r3, addr)                                         \
    asm volatile("ldmatrix.sync.aligned.m8n8.x4.shared.b16 {%0,%1,%2,%3}, [%4];" \
                 : "=r"(r0), "=r"(r1), "=r"(r2), "=r"(r3) : "r"(addr))

#define LDSM_X2(r0, r1, addr)                                                 \
    asm volatile("ldmatrix.sync.aligned.m8n8.x2.shared.b16 {%0,%1}, [%2];"    \
                 : "=r"(r0), "=r"(r1) : "r"(addr))

__device__ __forceinline__ void cp16(uint32_t* dst, const uint32_t* src) {
    uint32_t s = (uint32_t)__cvta_generic_to_shared(dst);
    asm volatile("cp.async.ca.shared.global [%0], [%1], 16;" :: "r"(s), "l"(src));
}
__device__ __forceinline__ uint32_t smem_u32(const void* p) {
    uint32_t a;
    asm("{ .reg .u64 t; cvta.to.shared.u64 t, %1; cvt.u32.u64 %0, t; }"
        : "=r"(a) : "l"(p));
    return a;
}

// =================== combined weight split (one launch) ===================
__global__ __launch_bounds__(256) void wsplit_all_kernel(
    const float* __restrict__ Wqkv, const float* __restrict__ Wo,
    const float* __restrict__ W1,   const float* __restrict__ W2,
    uint32_t* __restrict__ qh, uint32_t* __restrict__ ql,
    uint32_t* __restrict__ oh, uint32_t* __restrict__ ol,
    uint32_t* __restrict__ h1, uint32_t* __restrict__ l1,
    uint32_t* __restrict__ h2, uint32_t* __restrict__ l2)
{
    int i = blockIdx.x * 256 + threadIdx.x;
    if (i >= NW_TOT) return;
    const float* src;
    uint32_t *dh, *dl;
    int j = i;
    if (j < NW_QKV)                       { src = Wqkv; dh = qh; dl = ql; }
    else if ((j -= NW_QKV) < NW_O)        { src = Wo;   dh = oh; dl = ol; }
    else if ((j -= NW_O) < NW_1)          { src = W1;   dh = h1; dl = l1; }
    else { j -= NW_1;                       src = W2;   dh = h2; dl = l2; }
    float2 v = *(const float2*)&src[2 * j];
    split2(v.x, v.y, dh[j], dl[j]);
}

// =================== embedding (writes fp32 h + split) ===================
__global__ __launch_bounds__(128) void embed_kernel(
    const float* __restrict__ x, const int* __restrict__ t_idx,
    const int* __restrict__ sp_idx, const float* __restrict__ conv_w,
    const float* __restrict__ conv_b, const float* __restrict__ pos,
    const float* __restrict__ time_tab, const float* __restrict__ spat_tab,
    const float* __restrict__ cls)
{
    int token = blockIdx.x;
    int b = token / kS, s = token % kS;
    int e = threadIdx.x;
    float val;
    if (s < kLeads) {
        val = cls[s * kE + e] + pos[s * kE + e];
    } else {
        int l = s - kLeads;
        __shared__ float xs[kWin];
        if (e < kWin) xs[e] = x[((size_t)b * kSeq + l) * kWin + e];
        __syncthreads();
        float dot = 0.f;
        #pragma unroll 8
        for (int t = 0; t < kWin; t++) dot += xs[t] * conv_w[e * kWin + t];
        int ti = t_idx [b * kSeq + l];
        int si = sp_idx[b * kSeq + l];
        val = dot + conv_b[e] + pos[s * kE + e]
                  + time_tab[ti * kE + e] + spat_tab[si * kE + e];
    }
    g_h[(size_t)token * kE + e] = val;
    float vn = __shfl_down_sync(0xffffffffu, val, 1);
    if (!(e & 1)) {
        uint32_t h, l2;
        split2(val, vn, h, l2);
        g_hh[(size_t)token * EP + (e >> 1)] = h;
        g_hl[(size_t)token * EP + (e >> 1)] = l2;
    }
}

// =================== bf16x3 GEMM, full-K-panel staging ===================
// C[M,N] = A[M,2Kp] @ W[N,2Kp]^T + bias, inputs packed bf16 (h,l) pairs.
// BM=128 BN=64. Whole 64-pair (K=128) chunk staged at once -> ONE sync per
// chunk; inner loop = 8 k16-steps of unobstructed LDSM+MMA (deep ILP).
// QKV/O/FFN1: 1 chunk (single sync). FFN2: 4 chunks.
// mode: 0 = fp32 out, 1 = split out, 2 = relu + split out.
constexpr int BM = 128, BN = 64, CKP = 64;
constexpr int ASTR = 68;                   // pair stride; 68 mod 32 = 4 -> conflict-free
constexpr int GAW = BM * ASTR;             // 8704 words per A buffer
constexpr int GWW = BN * ASTR;             // 4352 words per W buffer
constexpr int GEMM_SMEM_BYTES = (2 * GAW + 2 * GWW) * 4;   // 104448

__global__ __launch_bounds__(256) void gemm_mma_kernel(
    const uint32_t* __restrict__ Ah, const uint32_t* __restrict__ Al,
    const uint32_t* __restrict__ Wh, const uint32_t* __restrict__ Wl,
    const float* __restrict__ bias,
    float* __restrict__ Cf, uint32_t* __restrict__ Ch, uint32_t* __restrict__ Cl,
    int M, int N, int Kp, int mode)
{
    extern __shared__ uint32_t gsm[];
    uint32_t gsmU = smem_u32(gsm);

    int t = threadIdx.x;
    int bm = blockIdx.y * BM, bn = blockIdx.x * BN;

    // staging mapping: A = 2 thr/row x 32 pairs (8 cp16); W = 4 thr/row x 16 pairs
    int aRow = t >> 1;               // 0..127
    int aOfs = (t & 1) * 32;         // 0 or 32 pairs
    int wRow = t >> 2;               // 0..63
    int wOfs = (t & 3) * 16;         // 0,16,32,48 pairs

    const uint32_t* ahp = Ah + (size_t)(bm + aRow) * Kp + aOfs;
    const uint32_t* alp = Al + (size_t)(bm + aRow) * Kp + aOfs;
    const uint32_t* whp = Wh + (size_t)(bn + wRow) * Kp + wOfs;
    const uint32_t* wlp = Wl + (size_t)(bn + wRow) * Kp + wOfs;

    int wid = t >> 5, lane = t & 31;
    int wm = (wid & 3) * 32;
    int wn = (wid >> 2) * 32;
    int grp = lane >> 2, q = lane & 3;

    // ldmatrix per-lane byte offsets
    uint32_t aOff = (uint32_t)(((wm + (lane & 15)) * ASTR + (lane >> 4) * 4) * 4);
    uint32_t wOff = (uint32_t)((2 * GAW + (wn + (lane >> 4) * 8 + (lane & 7)) * ASTR
                                + ((lane >> 3) & 1) * 4) * 4);

    float acc[2][4][4] = {};
    int nChunks = Kp >> 6;

    for (int ck = 0; ck < nChunks; ck++) {
        if (ck > 0) __syncthreads();   // previous chunk's reads done
        int o = ck * CKP;
        #pragma unroll
        for (int j = 0; j < 8; j++) {
            cp16(&gsm[aRow * ASTR + aOfs + j * 4],       ahp + o + j * 4);
            cp16(&gsm[GAW + aRow * ASTR + aOfs + j * 4], alp + o + j * 4);
        }
        #pragma unroll
        for (int j = 0; j < 4; j++) {
            cp16(&gsm[2*GAW + wRow * ASTR + wOfs + j * 4],       whp + o + j * 4);
            cp16(&gsm[2*GAW + GWW + wRow * ASTR + wOfs + j * 4], wlp + o + j * 4);
        }
        asm volatile("cp.async.commit_group;");
        asm volatile("cp.async.wait_group 0;");
        __syncthreads();

        #pragma unroll
        for (int ks = 0; ks < 8; ks++) {   // 8 k16 steps cover all 64 pairs
            uint32_t aA = gsmU + aOff + ks * 32;
            uint32_t ah0[4], ah1[4], al0[4], al1[4];
            LDSM_X4(ah0[0], ah0[1], ah0[2], ah0[3], aA);
            LDSM_X4(ah1[0], ah1[1], ah1[2], ah1[3], aA + 16 * ASTR * 4);
            LDSM_X4(al0[0], al0[1], al0[2], al0[3], aA + GAW * 4);
            LDSM_X4(al1[0], al1[1], al1[2], al1[3], aA + GAW * 4 + 16 * ASTR * 4);

            uint32_t wA = gsmU + wOff + ks * 32;
            uint32_t wh[8], wl[8];
            LDSM_X4(wh[0], wh[1], wh[2], wh[3], wA);
            LDSM_X4(wh[4], wh[5], wh[6], wh[7], wA + 16 * ASTR * 4);
            LDSM_X4(wl[0], wl[1], wl[2], wl[3], wA + GWW * 4);
            LDSM_X4(wl[4], wl[5], wl[6], wl[7], wA + GWW * 4 + 16 * ASTR * 4);

            #pragma unroll
            for (int nt = 0; nt < 4; nt++) {
                uint32_t bh0 = wh[2 * nt], bh1 = wh[2 * nt + 1];
                uint32_t bl0 = wl[2 * nt], bl1 = wl[2 * nt + 1];
                MMA_BF16(acc[0][nt], ah0, bh0, bh1);
                MMA_BF16(acc[0][nt], ah0, bl0, bl1);
                MMA_BF16(acc[0][nt], al0, bh0, bh1);
                MMA_BF16(acc[1][nt], ah1, bh0, bh1);
                MMA_BF16(acc[1][nt], ah1, bl0, bl1);
                MMA_BF16(acc[1][nt], al1, bh0, bh1);
            }
        }
    }

    int Np = N >> 1;
    #pragma unroll
    for (int mt = 0; mt < 2; mt++) {
        int row = bm + wm + mt * 16 + grp;
        #pragma unroll
        for (int nt = 0; nt < 4; nt++) {
            int col = bn + wn + nt * 8 + q * 2;
            float b0 = bias[col], b1 = bias[col + 1];
            float v00 = acc[mt][nt][0] + b0, v01 = acc[mt][nt][1] + b1;
            float v10 = acc[mt][nt][2] + b0, v11 = acc[mt][nt][3] + b1;
            if (mode == 2) {
                v00 = fmaxf(v00, 0.f); v01 = fmaxf(v01, 0.f);
                v10 = fmaxf(v10, 0.f); v11 = fmaxf(v11, 0.f);
            }
            if (mode == 0) {
                float2 o0 = make_float2(v00, v01);
                float2 o1 = make_float2(v10, v11);
                *(float2*)&Cf[(size_t)row * N + col]       = o0;
                *(float2*)&Cf[(size_t)(row + 8) * N + col] = o1;
            } else {
                int pidx = (col >> 1);
                uint32_t h0, l0, h1, l1;
                split2(v00, v01, h0, l0);
                split2(v10, v11, h1, l1);
                Ch[(size_t)row * Np + pidx]       = h0;
                Cl[(size_t)row * Np + pidx]       = l0;
                Ch[(size_t)(row + 8) * Np + pidx] = h1;
                Cl[(size_t)(row + 8) * Np + pidx] = l1;
            }
        }
    }
}

// =================== bf16x3 flash attention, prepacked qkv, ldmatrix =========
constexpr int KSTRP = 12;
constexpr int VSTR  = 140;
constexpr int ATT_KWORDS = kS * KSTRP;        // 3168
constexpr int ATT_VWORDS = kD * VSTR;         // 2240
constexpr int ATT_SMEM_BYTES = (2 * ATT_KWORDS + 2 * ATT_VWORDS) * 4;  // 43264

__global__ __launch_bounds__(256, 2) void attn_mma_kernel(
    const uint32_t* __restrict__ qkvh, const uint32_t* __restrict__ qkvl)
{
    extern __shared__ uint32_t asm_[];
    uint32_t* Kh  = asm_;
    uint32_t* Kl  = asm_ + ATT_KWORDS;
    uint32_t* Vth = asm_ + 2 * ATT_KWORDS;
    uint32_t* Vtl = asm_ + 2 * ATT_KWORDS + ATT_VWORDS;
    uint32_t KhU  = smem_u32(Kh);
    uint32_t VthU = smem_u32(Vth);

    int bh = blockIdx.x;
    int b = bh >> 3, head = bh & 7;
    int tid = threadIdx.x;
    const size_t tokbase = (size_t)b * kS;

    for (int i = tid; i < kS * 2; i += 256) {
        int s = i >> 1, c = (i & 1) * 4;
        const uint32_t* srch = qkvh + (tokbase + s) * QP + 64 + head * 8 + c;
        const uint32_t* srcl = qkvl + (tokbase + s) * QP + 64 + head * 8 + c;
        cp16(&Kh[s * KSTRP + c], srch);
        cp16(&Kl[s * KSTRP + c], srcl);
    }
    asm volatile("cp.async.commit_group;");
    for (int i = tid; i < 132 * 8; i += 256) {
        int j = i >> 3, pd = i & 7;
        size_t r0 = (tokbase + 2 * j) * QP + 128 + head * 8 + pd;
        size_t r1 = r0 + QP;
        uint32_t w0h = qkvh[r0], w1h = qkvh[r1];
        uint32_t w0l = qkvl[r0], w1l = qkvl[r1];
        Vth[(2 * pd)     * VSTR + j] = __byte_perm(w0h, w1h, 0x5410);
        Vth[(2 * pd + 1) * VSTR + j] = __byte_perm(w0h, w1h, 0x7632);
        Vtl[(2 * pd)     * VSTR + j] = __byte_perm(w0l, w1l, 0x5410);
        Vtl[(2 * pd + 1) * VSTR + j] = __byte_perm(w0l, w1l, 0x7632);
    }
    asm volatile("cp.async.wait_group 0;");
    __syncthreads();

    int wid = tid >> 5, lane = tid & 31;
    int grp = lane >> 2, q = lane & 3;

    uint32_t kOff  = (uint32_t)((((lane >> 4) * 8 + (lane & 7)) * KSTRP
                                 + ((lane >> 3) & 1) * 4) * 4);
    uint32_t kOff2 = (uint32_t)(((lane & 7) * KSTRP + ((lane >> 3) & 1) * 4) * 4);
    uint32_t vOff  = (uint32_t)((((lane >> 4) * 8 + (lane & 7)) * VSTR
                                 + ((lane >> 3) & 1) * 4) * 4);
    uint32_t vOff2 = (uint32_t)(((lane & 15) * VSTR) * 4);

    for (int mt = wid; mt < 17; mt += 8) {
        int r0 = mt * 16 + grp;
        int r1 = r0 + 8;
        bool v1 = (r1 < kS);

        uint32_t qh[4], ql[4];
        {
            size_t b0 = (tokbase + r0) * QP + head * 8;
            size_t b1 = (tokbase + (v1 ? r1 : r0)) * QP + head * 8;
            qh[0] = qkvh[b0 + q];     ql[0] = qkvl[b0 + q];
            qh[2] = qkvh[b0 + q + 4]; ql[2] = qkvl[b0 + q + 4];
            qh[1] = v1 ? qkvh[b1 + q]     : 0u;
            ql[1] = v1 ? qkvl[b1 + q]     : 0u;
            qh[3] = v1 ? qkvh[b1 + q + 4] : 0u;
            ql[3] = v1 ? qkvl[b1 + q + 4] : 0u;
        }

        float mA = -1e30f, mB = -1e30f, lA = 0.f, lB = 0.f;
        float O[2][4] = {};

        for (int ch = 0; ch < 3; ch++) {
            int n0 = ch * 88;
            int n0h = ch * 44;

            float sc[11][4];
            #pragma unroll
            for (int nt = 0; nt < 11; nt++) {
                sc[nt][0] = 0.f; sc[nt][1] = 0.f; sc[nt][2] = 0.f; sc[nt][3] = 0.f;
            }
            #pragma unroll
            for (int ntp = 0; ntp < 5; ntp++) {
                uint32_t aH = KhU + kOff + (uint32_t)((n0 + ntp * 16) * KSTRP * 4);
                uint32_t b0h, b1h, b2h, b3h, b0l, b1l, b2l, b3l;
                LDSM_X4(b0h, b1h, b2h, b3h, aH);
                LDSM_X4(b0l, b1l, b2l, b3l, aH + ATT_KWORDS * 4);
                MMA_BF16(sc[2*ntp],   qh, b0h, b1h);
                MMA_BF16(sc[2*ntp],   qh, b0l, b1l);
                MMA_BF16(sc[2*ntp],   ql, b0h, b1h);
                MMA_BF16(sc[2*ntp+1], qh, b2h, b3h);
                MMA_BF16(sc[2*ntp+1], qh, b2l, b3l);
                MMA_BF16(sc[2*ntp+1], ql, b2h, b3h);
            }
            {
                uint32_t aH = KhU + kOff2 + (uint32_t)((n0 + 80) * KSTRP * 4);
                uint32_t b0h, b1h, b0l, b1l;
                LDSM_X2(b0h, b1h, aH);
                LDSM_X2(b0l, b1l, aH + ATT_KWORDS * 4);
                MMA_BF16(sc[10], qh, b0h, b1h);
                MMA_BF16(sc[10], qh, b0l, b1l);
                MMA_BF16(sc[10], ql, b0h, b1h);
            }
            #pragma unroll
            for (int nt = 0; nt < 11; nt++) {
                sc[nt][0] *= 0.25f; sc[nt][1] *= 0.25f;
                sc[nt][2] *= 0.25f; sc[nt][3] *= 0.25f;
            }

            float cmA = -1e30f, cmB = -1e30f;
            #pragma unroll
            for (int nt = 0; nt < 11; nt++) {
                cmA = fmaxf(cmA, fmaxf(sc[nt][0], sc[nt][1]));
                cmB = fmaxf(cmB, fmaxf(sc[nt][2], sc[nt][3]));
            }
            cmA = fmaxf(cmA, __shfl_xor_sync(0xffffffffu, cmA, 1));
            cmA = fmaxf(cmA, __shfl_xor_sync(0xffffffffu, cmA, 2));
            cmB = fmaxf(cmB, __shfl_xor_sync(0xffffffffu, cmB, 1));
            cmB = fmaxf(cmB, __shfl_xor_sync(0xffffffffu, cmB, 2));

            float mnA = fmaxf(mA, cmA), mnB = fmaxf(mB, cmB);
            float aA = __expf(mA - mnA), aB = __expf(mB - mnB);
            mA = mnA; mB = mnB;

            float sA = 0.f, sB = 0.f;
            #pragma unroll
            for (int nt = 0; nt < 11; nt++) {
                sc[nt][0] = __expf(sc[nt][0] - mA);
                sc[nt][1] = __expf(sc[nt][1] - mA);
                sc[nt][2] = __expf(sc[nt][2] - mB);
                sc[nt][3] = __expf(sc[nt][3] - mB);
                sA += sc[nt][0] + sc[nt][1];
                sB += sc[nt][2] + sc[nt][3];
            }
            sA += __shfl_xor_sync(0xffffffffu, sA, 1);
            sA += __shfl_xor_sync(0xffffffffu, sA, 2);
            sB += __shfl_xor_sync(0xffffffffu, sB, 1);
            sB += __shfl_xor_sync(0xffffffffu, sB, 2);
            lA = lA * aA + sA;
            lB = lB * aB + sB;
            #pragma unroll
            for (int n2 = 0; n2 < 2; n2++) {
                O[n2][0] *= aA; O[n2][1] *= aA;
                O[n2][2] *= aB; O[n2][3] *= aB;
            }

            #pragma unroll
            for (int kt = 0; kt < 5; kt++) {
                uint32_t pah[4], pal[4];
                split2(sc[2*kt][0],   sc[2*kt][1],   pah[0], pal[0]);
                split2(sc[2*kt][2],   sc[2*kt][3],   pah[1], pal[1]);
                split2(sc[2*kt+1][0], sc[2*kt+1][1], pah[2], pal[2]);
                split2(sc[2*kt+1][2], sc[2*kt+1][3], pah[3], pal[3]);
                uint32_t vH = VthU + vOff + (uint32_t)((n0h + kt * 8) * 4);
                uint32_t b0h, b1h, b2h, b3h, b0l, b1l, b2l, b3l;
                LDSM_X4(b0h, b1h, b2h, b3h, vH);
                LDSM_X4(b0l, b1l, b2l, b3l, vH + ATT_VWORDS * 4);
                MMA_BF16(O[0], pah, b0h, b1h);
                MMA_BF16(O[0], pah, b0l, b1l);
                MMA_BF16(O[0], pal, b0h, b1h);
                MMA_BF16(O[1], pah, b2h, b3h);
                MMA_BF16(O[1], pah, b2l, b3l);
                MMA_BF16(O[1], pal, b2h, b3h);
            }
            {
                uint32_t a0h, a0l, a1h, a1l;
                split2(sc[10][0], sc[10][1], a0h, a0l);
                split2(sc[10][2], sc[10][3], a1h, a1l);
                uint32_t vH = VthU + vOff2 + (uint32_t)((n0h + 40) * 4);
                uint32_t b0h, b1h, b0l, b1l;
                LDSM_X2(b0h, b1h, vH);
                LDSM_X2(b0l, b1l, vH + ATT_VWORDS * 4);
                MMA_BF16_K8(O[0], a0h, a1h, b0h);
                MMA_BF16_K8(O[0], a0h, a1h, b0l);
                MMA_BF16_K8(O[0], a0l, a1l, b0h);
                MMA_BF16_K8(O[1], a0h, a1h, b1h);
                MMA_BF16_K8(O[1], a0h, a1h, b1l);
                MMA_BF16_K8(O[1], a0l, a1l, b1h);
            }
        }

        float iA = 1.0f / lA, iB = 1.0f / lB;
        #pragma unroll
        for (int n2 = 0; n2 < 2; n2++) {
            int pidx = head * 8 + n2 * 4 + q;
            uint32_t h, l;
            split2(O[n2][0] * iA, O[n2][1] * iA, h, l);
            g_atth[(tokbase + r0) * EP + pidx] = h;
            g_attl[(tokbase + r0) * EP + pidx] = l;
            if (v1) {
                split2(O[n2][2] * iB, O[n2][3] * iB, h, l);
                g_atth[(tokbase + r1) * EP + pidx] = h;
                g_attl[(tokbase + r1) * EP + pidx] = l;
            }
        }
    }
}

// =================== fused residual-add + LayerNorm (+ split out) ============
__global__ __launch_bounds__(256) void add_ln_kernel(
    const float* hin, const float* __restrict__ delta,
    const float* __restrict__ g, const float* __restrict__ beta,
    float* hout, int wsplit)
{
    int row  = blockIdx.x * 8 + (threadIdx.x >> 5);
    int lane = threadIdx.x & 31;
    size_t base = (size_t)row * kE;

    float4 hv = *reinterpret_cast<const float4*>(&hin  [base + lane * 4]);
    float4 dv = *reinterpret_cast<const float4*>(&delta[base + lane * 4]);
    float v0 = hv.x + dv.x, v1 = hv.y + dv.y, v2 = hv.z + dv.z, v3 = hv.w + dv.w;

    float s = v0 + v1 + v2 + v3;
    #pragma unroll
    for (int o = 16; o; o >>= 1) s += __shfl_xor_sync(0xffffffffu, s, o);
    float mean = s * (1.0f / kE);

    float d0 = v0 - mean, d1 = v1 - mean, d2 = v2 - mean, d3 = v3 - mean;
    float sq = d0 * d0 + d1 * d1 + d2 * d2 + d3 * d3;
    #pragma unroll
    for (int o = 16; o; o >>= 1) sq += __shfl_xor_sync(0xffffffffu, sq, o);
    float rstd = rsqrtf(sq * (1.0f / kE) + 1e-5f);

    float4 gv = *reinterpret_cast<const float4*>(&g   [lane * 4]);
    float4 bv = *reinterpret_cast<const float4*>(&beta[lane * 4]);
    float4 ov;
    ov.x = d0 * rstd * gv.x + bv.x;
    ov.y = d1 * rstd * gv.y + bv.y;
    ov.z = d2 * rstd * gv.z + bv.z;
    ov.w = d3 * rstd * gv.w + bv.w;
    *reinterpret_cast<float4*>(&hout[base + lane * 4]) = ov;

    if (wsplit) {
        uint32_t h0, l0, h1, l1;
        split2(ov.x, ov.y, h0, l0);
        split2(ov.z, ov.w, h1, l1);
        size_t pb = (size_t)row * EP + lane * 2;
        g_hh[pb] = h0;     g_hl[pb] = l0;
        g_hh[pb + 1] = h1; g_hl[pb + 1] = l1;
    }
}

// =================== launch ===================
extern "C" void kernel_launch(void* const* d_in, const int* in_sizes, int n_in,
                              void* d_out, int out_size)
{
    const float* x        = (const float*)d_in[0];
    const int*   t_idx    = (const int*)  d_in[1];
    const int*   sp_idx   = (const int*)  d_in[2];
    const float* conv_w   = (const float*)d_in[3];
    const float* conv_b   = (const float*)d_in[4];
    const float* pos      = (const float*)d_in[5];
    const float* time_tab = (const float*)d_in[6];
    const float* spat_tab = (const float*)d_in[7];
    const float* cls      = (const float*)d_in[8];
    const float* Wqkv     = (const float*)d_in[9];
    const float* bqkv     = (const float*)d_in[10];
    const float* Wo       = (const float*)d_in[11];
    const float* bo       = (const float*)d_in[12];
    const float* W1       = (const float*)d_in[13];
    const float* b1       = (const float*)d_in[14];
    const float* W2       = (const float*)d_in[15];
    const float* b2       = (const float*)d_in[16];
    const float* ln1g     = (const float*)d_in[17];
    const float* ln1b     = (const float*)d_in[18];
    const float* ln2g     = (const float*)d_in[19];
    const float* ln2b     = (const float*)d_in[20];
    float* out = (float*)d_out;

    float *p_h, *p_proj;
    uint32_t *p_hh, *p_hl, *p_qkvh, *p_qkvl, *p_atth, *p_attl, *p_ff1h, *p_ff1l;
    uint32_t *p_wqkvh, *p_wqkvl, *p_woh, *p_wol, *p_w1h, *p_w1l, *p_w2h, *p_w2l;
    cudaGetSymbolAddress((void**)&p_h,     g_h);
    cudaGetSymbolAddress((void**)&p_proj,  g_proj);
    cudaGetSymbolAddress((void**)&p_hh,    g_hh);
    cudaGetSymbolAddress((void**)&p_hl,    g_hl);
    cudaGetSymbolAddress((void**)&p_qkvh,  g_qkvh);
    cudaGetSymbolAddress((void**)&p_qkvl,  g_qkvl);
    cudaGetSymbolAddress((void**)&p_atth,  g_atth);
    cudaGetSymbolAddress((void**)&p_attl,  g_attl);
    cudaGetSymbolAddress((void**)&p_ff1h,  g_ff1h);
    cudaGetSymbolAddress((void**)&p_ff1l,  g_ff1l);
    cudaGetSymbolAddress((void**)&p_wqkvh, g_wqkvh);
    cudaGetSymbolAddress((void**)&p_wqkvl, g_wqkvl);
    cudaGetSymbolAddress((void**)&p_woh,   g_woh);
    cudaGetSymbolAddress((void**)&p_wol,   g_wol);
    cudaGetSymbolAddress((void**)&p_w1h,   g_w1h);
    cudaGetSymbolAddress((void**)&p_w1l,   g_w1l);
    cudaGetSymbolAddress((void**)&p_w2h,   g_w2h);
    cudaGetSymbolAddress((void**)&p_w2l,   g_w2l);

    cudaFuncSetAttribute(gemm_mma_kernel,
        cudaFuncAttributeMaxDynamicSharedMemorySize, GEMM_SMEM_BYTES);
    cudaFuncSetAttribute(attn_mma_kernel,
        cudaFuncAttributeMaxDynamicSharedMemorySize, ATT_SMEM_BYTES);

    // one-time weight splits (single launch)
    wsplit_all_kernel<<<(NW_TOT + 255) / 256, 256>>>(
        Wqkv, Wo, W1, W2,
        p_wqkvh, p_wqkvl, p_woh, p_wol, p_w1h, p_w1l, p_w2h, p_w2l);

    embed_kernel<<<kM, 128>>>(x, t_idx, sp_idx, conv_w, conv_b, pos,
                              time_tab, spat_tab, cls);

    for (int i = 0; i < kLayers; i++) {
        // QKV: [M,128] -> [M,384]  (split output)
        gemm_mma_kernel<<<dim3(384 / BN, kM / BM), 256, GEMM_SMEM_BYTES>>>(
            p_hh, p_hl, p_wqkvh + (size_t)i * 384 * EP, p_wqkvl + (size_t)i * 384 * EP,
            bqkv + (size_t)i * 384, nullptr, p_qkvh, p_qkvl, kM, 384, EP, 1);

        // attention -> att split
        attn_mma_kernel<<<kB * kH, 256, ATT_SMEM_BYTES>>>(p_qkvh, p_qkvl);

        // O-proj: [M,128] -> [M,128]  (fp32 output)
        gemm_mma_kernel<<<dim3(kE / BN, kM / BM), 256, GEMM_SMEM_BYTES>>>(
            p_atth, p_attl, p_woh + (size_t)i * kE * EP, p_wol + (size_t)i * kE * EP,
            bo + (size_t)i * kE, p_proj, nullptr, nullptr, kM, kE, EP, 0);

        // h = LN(h + o), emit split
        add_ln_kernel<<<kM / 8, 256>>>(p_h, p_proj,
            ln1g + (size_t)i * kE, ln1b + (size_t)i * kE, p_h, 1);

        // FFN1 + relu: [M,128] -> [M,512]  (split output)
        gemm_mma_kernel<<<dim3(kFF / BN, kM / BM), 256, GEMM_SMEM_BYTES>>>(
            p_hh, p_hl, p_w1h + (size_t)i * kFF * EP, p_w1l + (size_t)i * kFF * EP,
            b1 + (size_t)i * kFF, nullptr, p_ff1h, p_ff1l, kM, kFF, EP, 2);

        // FFN2: [M,512] -> [M,128]  (fp32 output; 4 chunks)
        gemm_mma_kernel<<<dim3(kE / BN, kM / BM), 256, GEMM_SMEM_BYTES>>>(
            p_ff1h, p_ff1l, p_w2h + (size_t)i * kE * FP, p_w2l + (size_t)i * kE * FP,
            b2 + (size_t)i * kE, p_proj, nullptr, nullptr, kM, kE, FP, 0);

        // h = LN(h + ff); last layer writes d_out
        float* dst = (i == kLayers - 1) ? out : p_h;
        add_ln_kernel<<<kM / 8, 256>>>(p_h, p_proj,
            ln2g + (size_t)i * kE, ln2b + (size_t)i * kE, dst,
            (i == kLayers - 1) ? 0 : 1);
    }
}

// round 15
// speedup vs baseline: 1.3571x; 1.3571x over previous
#include <cuda_runtime.h>
#include <cuda_bf16.h>
#include <cstdint>

// ---------------- problem constants ----------------
constexpr int kB      = 128;
constexpr int kSeq    = 252;
constexpr int kWin    = 96;
constexpr int kLeads  = 12;
constexpr int kS      = 264;   // kSeq + kLeads
constexpr int kE      = 128;
constexpr int kH      = 8;
constexpr int kD      = 16;    // kE / kH
constexpr int kFF     = 512;
constexpr int kLayers = 12;
constexpr int kM      = kB * kS;   // 33792 tokens

// pair-widths (K/2) for packed bf16 hi/lo activations
constexpr int EP  = kE / 2;    // 64
constexpr int QP  = 192;       // 384/2
constexpr int FP  = kFF / 2;   // 256

// ---------------- scratch (device globals; no allocation allowed) ------------
__device__ float g_h   [kM * kE];   // residual stream (fp32)
__device__ float g_proj[kM * kE];   // O-proj / FFN2 fp32 outputs
__device__ uint32_t g_hh  [kM * EP],  g_hl  [kM * EP];
__device__ uint32_t g_qkvh[kM * QP],  g_qkvl[kM * QP];
__device__ uint32_t g_atth[kM * EP],  g_attl[kM * EP];
__device__ uint32_t g_ff1h[kM * FP],  g_ff1l[kM * FP];
__device__ uint32_t g_wqkvh[kLayers * 384 * EP], g_wqkvl[kLayers * 384 * EP];
__device__ uint32_t g_woh  [kLayers * kE  * EP], g_wol  [kLayers * kE  * EP];
__device__ uint32_t g_w1h  [kLayers * kFF * EP], g_w1l  [kLayers * kFF * EP];
__device__ uint32_t g_w2h  [kLayers * kE  * FP], g_w2l  [kLayers * kE  * FP];

// split sizes (pairs)
constexpr int NW_QKV = kLayers * 384 * EP;
constexpr int NW_O   = kLayers * kE  * EP;
constexpr int NW_1   = kLayers * kFF * EP;
constexpr int NW_2   = kLayers * kE  * FP;
constexpr int NW_TOT = NW_QKV + NW_O + NW_1 + NW_2;

// ---------------- bf16 split helpers ----------------
__device__ __forceinline__ float bhi(float x) {
    return __bfloat162float(__float2bfloat16(x));
}
__device__ __forceinline__ uint32_t packbf(float a, float b) {
    __nv_bfloat162 t;
    t.x = __float2bfloat16(a);
    t.y = __float2bfloat16(b);
    return *reinterpret_cast<uint32_t*>(&t);
}
__device__ __forceinline__ void split2(float a, float b, uint32_t& h, uint32_t& l) {
    float ha = bhi(a), hb = bhi(b);
    h = packbf(a, b);
    l = packbf(a - ha, b - hb);
}

#define MMA_BF16(d, a, b0, b1)                                                \
    asm volatile("mma.sync.aligned.m16n8k16.row.col.f32.bf16.bf16.f32 "       \
                 "{%0,%1,%2,%3}, {%4,%5,%6,%7}, {%8,%9}, {%0,%1,%2,%3};"      \
                 : "+f"(d[0]), "+f"(d[1]), "+f"(d[2]), "+f"(d[3])             \
                 : "r"(a[0]), "r"(a[1]), "r"(a[2]), "r"(a[3]),                \
                   "r"(b0), "r"(b1))

#define MMA_BF16_K8(d, a0, a1, b0)                                            \
    asm volatile("mma.sync.aligned.m16n8k8.row.col.f32.bf16.bf16.f32 "        \
                 "{%0,%1,%2,%3}, {%4,%5}, {%6}, {%0,%1,%2,%3};"               \
                 : "+f"(d[0]), "+f"(d[1]), "+f"(d[2]), "+f"(d[3])             \
                 : "r"(a0), "r"(a1), "r"(b0))

#define LDSM_X4(r0, r1, r2, r3, addr)                                         \
    asm volatile("ldmatrix.sync.aligned.m8n8.x4.shared.b16 {%0,%1,%2,%3}, [%4];" \
                 : "=r"(r0), "=r"(r1), "=r"(r2), "=r"(r3) : "r"(addr))

#define LDSM_X2(r0, r1, addr)                                                 \
    asm volatile("ldmatrix.sync.aligned.m8n8.x2.shared.b16 {%0,%1}, [%2];"    \
                 : "=r"(r0), "=r"(r1) : "r"(addr))

__device__ __forceinline__ void cp16(uint32_t* dst, const uint32_t* src) {
    uint32_t s = (uint32_t)__cvta_generic_to_shared(dst);
    asm volatile("cp.async.ca.shared.global [%0], [%1], 16;" :: "r"(s), "l"(src));
}
__device__ __forceinline__ uint32_t smem_u32(const void* p) {
    uint32_t a;
    asm("{ .reg .u64 t; cvta.to.shared.u64 t, %1; cvt.u32.u64 %0, t; }"
        : "=r"(a) : "l"(p));
    return a;
}

// =================== combined weight split (one launch) ===================
__global__ __launch_bounds__(256) void wsplit_all_kernel(
    const float* __restrict__ Wqkv, const float* __restrict__ Wo,
    const float* __restrict__ W1,   const float* __restrict__ W2,
    uint32_t* __restrict__ qh, uint32_t* __restrict__ ql,
    uint32_t* __restrict__ oh, uint32_t* __restrict__ ol,
    uint32_t* __restrict__ h1, uint32_t* __restrict__ l1,
    uint32_t* __restrict__ h2, uint32_t* __restrict__ l2)
{
    int i = blockIdx.x * 256 + threadIdx.x;
    if (i >= NW_TOT) return;
    const float* src;
    uint32_t *dh, *dl;
    int j = i;
    if (j < NW_QKV)                       { src = Wqkv; dh = qh; dl = ql; }
    else if ((j -= NW_QKV) < NW_O)        { src = Wo;   dh = oh; dl = ol; }
    else if ((j -= NW_O) < NW_1)          { src = W1;   dh = h1; dl = l1; }
    else { j -= NW_1;                       src = W2;   dh = h2; dl = l2; }
    float2 v = *(const float2*)&src[2 * j];
    split2(v.x, v.y, dh[j], dl[j]);
}

// =================== embedding (writes fp32 h + split) ===================
__global__ __launch_bounds__(128) void embed_kernel(
    const float* __restrict__ x, const int* __restrict__ t_idx,
    const int* __restrict__ sp_idx, const float* __restrict__ conv_w,
    const float* __restrict__ conv_b, const float* __restrict__ pos,
    const float* __restrict__ time_tab, const float* __restrict__ spat_tab,
    const float* __restrict__ cls)
{
    int token = blockIdx.x;
    int b = token / kS, s = token % kS;
    int e = threadIdx.x;
    float val;
    if (s < kLeads) {
        val = cls[s * kE + e] + pos[s * kE + e];
    } else {
        int l = s - kLeads;
        __shared__ float xs[kWin];
        if (e < kWin) xs[e] = x[((size_t)b * kSeq + l) * kWin + e];
        __syncthreads();
        float dot = 0.f;
        #pragma unroll 8
        for (int t = 0; t < kWin; t++) dot += xs[t] * conv_w[e * kWin + t];
        int ti = t_idx [b * kSeq + l];
        int si = sp_idx[b * kSeq + l];
        val = dot + conv_b[e] + pos[s * kE + e]
                  + time_tab[ti * kE + e] + spat_tab[si * kE + e];
    }
    g_h[(size_t)token * kE + e] = val;
    float vn = __shfl_down_sync(0xffffffffu, val, 1);
    if (!(e & 1)) {
        uint32_t h, l2;
        split2(val, vn, h, l2);
        g_hh[(size_t)token * EP + (e >> 1)] = h;
        g_hl[(size_t)token * EP + (e >> 1)] = l2;
    }
}

// =================== bf16x3 GEMM, 3-stage cp.async + ldmatrix ================
// C[M,N] = A[M,2Kp] @ W[N,2Kp]^T + bias, inputs packed bf16 (h,l) pairs.
// BM=128 BN=64, BKP=16 pairs (K=32) per iter, 256 thr, warp tile 32x32.
// 3-stage pipeline: loads run 2 iterations ahead of compute.
// mode: 0 = fp32 out, 1 = split out, 2 = relu + split out.
constexpr int BM = 128, BN = 64, BKP = 16;
constexpr int PSTR = 20;                  // smem row stride (pairs), pad 4
constexpr int GA = BM * PSTR;             // 2560
constexpr int GW = BN * PSTR;             // 1280
constexpr int GBUF = 2 * GA + 2 * GW;     // 7680 words per stage
constexpr int NSTAGE = 3;
constexpr int GEMM_SMEM_BYTES = NSTAGE * GBUF * 4;   // 92160

__global__ __launch_bounds__(256) void gemm_mma_kernel(
    const uint32_t* __restrict__ Ah, const uint32_t* __restrict__ Al,
    const uint32_t* __restrict__ Wh, const uint32_t* __restrict__ Wl,
    const float* __restrict__ bias,
    float* __restrict__ Cf, uint32_t* __restrict__ Ch, uint32_t* __restrict__ Cl,
    int M, int N, int Kp, int mode)
{
    extern __shared__ uint32_t gsm[];
    uint32_t gsmU = smem_u32(gsm);

    int t = threadIdx.x;
    int bm = blockIdx.y * BM, bn = blockIdx.x * BN;

    // staging mapping
    int saRow = t >> 1;              // 0..127
    int saOfs = (t & 1) * 8;         // 0 or 8
    int swRow = t >> 2;              // 0..63
    int swOfs = (t & 3) * 4;         // 0,4,8,12

    const uint32_t* ahp = Ah + (size_t)(bm + saRow) * Kp + saOfs;
    const uint32_t* alp = Al + (size_t)(bm + saRow) * Kp + saOfs;
    const uint32_t* whp = Wh + (size_t)(bn + swRow) * Kp + swOfs;
    const uint32_t* wlp = Wl + (size_t)(bn + swRow) * Kp + swOfs;

    int wid = t >> 5, lane = t & 31;
    int wm = (wid & 3) * 32;
    int wn = (wid >> 2) * 32;
    int grp = lane >> 2, q = lane & 3;

    // ldmatrix per-lane byte offsets (relative to stage-buffer base)
    uint32_t aOff = (uint32_t)(((wm + (lane & 15)) * PSTR + (lane >> 4) * 4) * 4);
    uint32_t wOff = (uint32_t)((2 * GA + (wn + (lane >> 4) * 8 + (lane & 7)) * PSTR
                                + ((lane >> 3) & 1) * 4) * 4);

    float acc[2][4][4] = {};
    int nIter = Kp / BKP;

    // prologue: stage iters 0 and 1 into buffers 0 and 1
    #pragma unroll
    for (int p = 0; p < 2; p++) {
        uint32_t* B = gsm + p * GBUF;
        int o = p * BKP;
        cp16(&B[saRow * PSTR + saOfs],             ahp + o);
        cp16(&B[saRow * PSTR + saOfs + 4],         ahp + o + 4);
        cp16(&B[GA + saRow * PSTR + saOfs],        alp + o);
        cp16(&B[GA + saRow * PSTR + saOfs + 4],    alp + o + 4);
        cp16(&B[2*GA + swRow * PSTR + swOfs],      whp + o);
        cp16(&B[2*GA + GW + swRow * PSTR + swOfs], wlp + o);
        asm volatile("cp.async.commit_group;");
    }

    int bufC = 0;        // compute buffer for iter it
    int bufS = 2;        // stage buffer for iter it+2

    for (int it = 0; it < nIter; it++) {
        if (it + 1 < nIter) {
            asm volatile("cp.async.wait_group 1;");
        } else {
            asm volatile("cp.async.wait_group 0;");
        }
        __syncthreads();

        if (it + 2 < nIter) {
            uint32_t* B = gsm + bufS * GBUF;
            int o = (it + 2) * BKP;
            cp16(&B[saRow * PSTR + saOfs],             ahp + o);
            cp16(&B[saRow * PSTR + saOfs + 4],         ahp + o + 4);
            cp16(&B[GA + saRow * PSTR + saOfs],        alp + o);
            cp16(&B[GA + saRow * PSTR + saOfs + 4],    alp + o + 4);
            cp16(&B[2*GA + swRow * PSTR + swOfs],      whp + o);
            cp16(&B[2*GA + GW + swRow * PSTR + swOfs], wlp + o);
            asm volatile("cp.async.commit_group;");
            bufS = (bufS == 2) ? 0 : bufS + 1;
        }

        uint32_t base = gsmU + (uint32_t)(bufC * (GBUF * 4));
        bufC = (bufC == 2) ? 0 : bufC + 1;

        #pragma unroll
        for (int ks = 0; ks < 2; ks++) {
            uint32_t aA = base + aOff + ks * 32;
            uint32_t ah0[4], ah1[4], al0[4], al1[4];
            LDSM_X4(ah0[0], ah0[1], ah0[2], ah0[3], aA);
            LDSM_X4(ah1[0], ah1[1], ah1[2], ah1[3], aA + 16 * PSTR * 4);
            LDSM_X4(al0[0], al0[1], al0[2], al0[3], aA + GA * 4);
            LDSM_X4(al1[0], al1[1], al1[2], al1[3], aA + GA * 4 + 16 * PSTR * 4);

            uint32_t wA = base + wOff + ks * 32;
            uint32_t wh[8], wl[8];
            LDSM_X4(wh[0], wh[1], wh[2], wh[3], wA);
            LDSM_X4(wh[4], wh[5], wh[6], wh[7], wA + 16 * PSTR * 4);
            LDSM_X4(wl[0], wl[1], wl[2], wl[3], wA + GW * 4);
            LDSM_X4(wl[4], wl[5], wl[6], wl[7], wA + GW * 4 + 16 * PSTR * 4);

            #pragma unroll
            for (int nt = 0; nt < 4; nt++) {
                uint32_t bh0 = wh[2 * nt], bh1 = wh[2 * nt + 1];
                uint32_t bl0 = wl[2 * nt], bl1 = wl[2 * nt + 1];
                MMA_BF16(acc[0][nt], ah0, bh0, bh1);
                MMA_BF16(acc[0][nt], ah0, bl0, bl1);
                MMA_BF16(acc[0][nt], al0, bh0, bh1);
                MMA_BF16(acc[1][nt], ah1, bh0, bh1);
                MMA_BF16(acc[1][nt], ah1, bl0, bl1);
                MMA_BF16(acc[1][nt], al1, bh0, bh1);
            }
        }
        __syncthreads();
    }

    int Np = N >> 1;
    #pragma unroll
    for (int mt = 0; mt < 2; mt++) {
        int row = bm + wm + mt * 16 + grp;
        #pragma unroll
        for (int nt = 0; nt < 4; nt++) {
            int col = bn + wn + nt * 8 + q * 2;
            float b0 = bias[col], b1 = bias[col + 1];
            float v00 = acc[mt][nt][0] + b0, v01 = acc[mt][nt][1] + b1;
            float v10 = acc[mt][nt][2] + b0, v11 = acc[mt][nt][3] + b1;
            if (mode == 2) {
                v00 = fmaxf(v00, 0.f); v01 = fmaxf(v01, 0.f);
                v10 = fmaxf(v10, 0.f); v11 = fmaxf(v11, 0.f);
            }
            if (mode == 0) {
                float2 o0 = make_float2(v00, v01);
                float2 o1 = make_float2(v10, v11);
                *(float2*)&Cf[(size_t)row * N + col]       = o0;
                *(float2*)&Cf[(size_t)(row + 8) * N + col] = o1;
            } else {
                int pidx = (col >> 1);
                uint32_t h0, l0, h1, l1;
                split2(v00, v01, h0, l0);
                split2(v10, v11, h1, l1);
                Ch[(size_t)row * Np + pidx]       = h0;
                Cl[(size_t)row * Np + pidx]       = l0;
                Ch[(size_t)(row + 8) * Np + pidx] = h1;
                Cl[(size_t)(row + 8) * Np + pidx] = l1;
            }
        }
    }
}

// =================== bf16x3 flash attention, prepacked qkv, ldmatrix =========
constexpr int KSTRP = 12;
constexpr int VSTR  = 140;
constexpr int ATT_KWORDS = kS * KSTRP;        // 3168
constexpr int ATT_VWORDS = kD * VSTR;         // 2240
constexpr int ATT_SMEM_BYTES = (2 * ATT_KWORDS + 2 * ATT_VWORDS) * 4;  // 43264

__global__ __launch_bounds__(256, 2) void attn_mma_kernel(
    const uint32_t* __restrict__ qkvh, const uint32_t* __restrict__ qkvl)
{
    extern __shared__ uint32_t asm_[];
    uint32_t* Kh  = asm_;
    uint32_t* Kl  = asm_ + ATT_KWORDS;
    uint32_t* Vth = asm_ + 2 * ATT_KWORDS;
    uint32_t* Vtl = asm_ + 2 * ATT_KWORDS + ATT_VWORDS;
    uint32_t KhU  = smem_u32(Kh);
    uint32_t VthU = smem_u32(Vth);

    int bh = blockIdx.x;
    int b = bh >> 3, head = bh & 7;
    int tid = threadIdx.x;
    const size_t tokbase = (size_t)b * kS;

    for (int i = tid; i < kS * 2; i += 256) {
        int s = i >> 1, c = (i & 1) * 4;
        const uint32_t* srch = qkvh + (tokbase + s) * QP + 64 + head * 8 + c;
        const uint32_t* srcl = qkvl + (tokbase + s) * QP + 64 + head * 8 + c;
        cp16(&Kh[s * KSTRP + c], srch);
        cp16(&Kl[s * KSTRP + c], srcl);
    }
    asm volatile("cp.async.commit_group;");
    for (int i = tid; i < 132 * 8; i += 256) {
        int j = i >> 3, pd = i & 7;
        size_t r0 = (tokbase + 2 * j) * QP + 128 + head * 8 + pd;
        size_t r1 = r0 + QP;
        uint32_t w0h = qkvh[r0], w1h = qkvh[r1];
        uint32_t w0l = qkvl[r0], w1l = qkvl[r1];
        Vth[(2 * pd)     * VSTR + j] = __byte_perm(w0h, w1h, 0x5410);
        Vth[(2 * pd + 1) * VSTR + j] = __byte_perm(w0h, w1h, 0x7632);
        Vtl[(2 * pd)     * VSTR + j] = __byte_perm(w0l, w1l, 0x5410);
        Vtl[(2 * pd + 1) * VSTR + j] = __byte_perm(w0l, w1l, 0x7632);
    }
    asm volatile("cp.async.wait_group 0;");
    __syncthreads();

    int wid = tid >> 5, lane = tid & 31;
    int grp = lane >> 2, q = lane & 3;

    uint32_t kOff  = (uint32_t)((((lane >> 4) * 8 + (lane & 7)) * KSTRP
                                 + ((lane >> 3) & 1) * 4) * 4);
    uint32_t kOff2 = (uint32_t)(((lane & 7) * KSTRP + ((lane >> 3) & 1) * 4) * 4);
    uint32_t vOff  = (uint32_t)((((lane >> 4) * 8 + (lane & 7)) * VSTR
                                 + ((lane >> 3) & 1) * 4) * 4);
    uint32_t vOff2 = (uint32_t)(((lane & 15) * VSTR) * 4);

    for (int mt = wid; mt < 17; mt += 8) {
        int r0 = mt * 16 + grp;
        int r1 = r0 + 8;
        bool v1 = (r1 < kS);

        uint32_t qh[4], ql[4];
        {
            size_t b0 = (tokbase + r0) * QP + head * 8;
            size_t b1 = (tokbase + (v1 ? r1 : r0)) * QP + head * 8;
            qh[0] = qkvh[b0 + q];     ql[0] = qkvl[b0 + q];
            qh[2] = qkvh[b0 + q + 4]; ql[2] = qkvl[b0 + q + 4];
            qh[1] = v1 ? qkvh[b1 + q]     : 0u;
            ql[1] = v1 ? qkvl[b1 + q]     : 0u;
            qh[3] = v1 ? qkvh[b1 + q + 4] : 0u;
            ql[3] = v1 ? qkvl[b1 + q + 4] : 0u;
        }

        float mA = -1e30f, mB = -1e30f, lA = 0.f, lB = 0.f;
        float O[2][4] = {};

        for (int ch = 0; ch < 3; ch++) {
            int n0 = ch * 88;
            int n0h = ch * 44;

            float sc[11][4];
            #pragma unroll
            for (int nt = 0; nt < 11; nt++) {
                sc[nt][0] = 0.f; sc[nt][1] = 0.f; sc[nt][2] = 0.f; sc[nt][3] = 0.f;
            }
            #pragma unroll
            for (int ntp = 0; ntp < 5; ntp++) {
                uint32_t aH = KhU + kOff + (uint32_t)((n0 + ntp * 16) * KSTRP * 4);
                uint32_t b0h, b1h, b2h, b3h, b0l, b1l, b2l, b3l;
                LDSM_X4(b0h, b1h, b2h, b3h, aH);
                LDSM_X4(b0l, b1l, b2l, b3l, aH + ATT_KWORDS * 4);
                MMA_BF16(sc[2*ntp],   qh, b0h, b1h);
                MMA_BF16(sc[2*ntp],   qh, b0l, b1l);
                MMA_BF16(sc[2*ntp],   ql, b0h, b1h);
                MMA_BF16(sc[2*ntp+1], qh, b2h, b3h);
                MMA_BF16(sc[2*ntp+1], qh, b2l, b3l);
                MMA_BF16(sc[2*ntp+1], ql, b2h, b3h);
            }
            {
                uint32_t aH = KhU + kOff2 + (uint32_t)((n0 + 80) * KSTRP * 4);
                uint32_t b0h, b1h, b0l, b1l;
                LDSM_X2(b0h, b1h, aH);
                LDSM_X2(b0l, b1l, aH + ATT_KWORDS * 4);
                MMA_BF16(sc[10], qh, b0h, b1h);
                MMA_BF16(sc[10], qh, b0l, b1l);
                MMA_BF16(sc[10], ql, b0h, b1h);
            }
            #pragma unroll
            for (int nt = 0; nt < 11; nt++) {
                sc[nt][0] *= 0.25f; sc[nt][1] *= 0.25f;
                sc[nt][2] *= 0.25f; sc[nt][3] *= 0.25f;
            }

            float cmA = -1e30f, cmB = -1e30f;
            #pragma unroll
            for (int nt = 0; nt < 11; nt++) {
                cmA = fmaxf(cmA, fmaxf(sc[nt][0], sc[nt][1]));
                cmB = fmaxf(cmB, fmaxf(sc[nt][2], sc[nt][3]));
            }
            cmA = fmaxf(cmA, __shfl_xor_sync(0xffffffffu, cmA, 1));
            cmA = fmaxf(cmA, __shfl_xor_sync(0xffffffffu, cmA, 2));
            cmB = fmaxf(cmB, __shfl_xor_sync(0xffffffffu, cmB, 1));
            cmB = fmaxf(cmB, __shfl_xor_sync(0xffffffffu, cmB, 2));

            float mnA = fmaxf(mA, cmA), mnB = fmaxf(mB, cmB);
            float aA = __expf(mA - mnA), aB = __expf(mB - mnB);
            mA = mnA; mB = mnB;

            float sA = 0.f, sB = 0.f;
            #pragma unroll
            for (int nt = 0; nt < 11; nt++) {
                sc[nt][0] = __expf(sc[nt][0] - mA);
                sc[nt][1] = __expf(sc[nt][1] - mA);
                sc[nt][2] = __expf(sc[nt][2] - mB);
                sc[nt][3] = __expf(sc[nt][3] - mB);
                sA += sc[nt][0] + sc[nt][1];
                sB += sc[nt][2] + sc[nt][3];
            }
            sA += __shfl_xor_sync(0xffffffffu, sA, 1);
            sA += __shfl_xor_sync(0xffffffffu, sA, 2);
            sB += __shfl_xor_sync(0xffffffffu, sB, 1);
            sB += __shfl_xor_sync(0xffffffffu, sB, 2);
            lA = lA * aA + sA;
            lB = lB * aB + sB;
            #pragma unroll
            for (int n2 = 0; n2 < 2; n2++) {
                O[n2][0] *= aA; O[n2][1] *= aA;
                O[n2][2] *= aB; O[n2][3] *= aB;
            }

            #pragma unroll
            for (int kt = 0; kt < 5; kt++) {
                uint32_t pah[4], pal[4];
                split2(sc[2*kt][0],   sc[2*kt][1],   pah[0], pal[0]);
                split2(sc[2*kt][2],   sc[2*kt][3],   pah[1], pal[1]);
                split2(sc[2*kt+1][0], sc[2*kt+1][1], pah[2], pal[2]);
                split2(sc[2*kt+1][2], sc[2*kt+1][3], pah[3], pal[3]);
                uint32_t vH = VthU + vOff + (uint32_t)((n0h + kt * 8) * 4);
                uint32_t b0h, b1h, b2h, b3h, b0l, b1l, b2l, b3l;
                LDSM_X4(b0h, b1h, b2h, b3h, vH);
                LDSM_X4(b0l, b1l, b2l, b3l, vH + ATT_VWORDS * 4);
                MMA_BF16(O[0], pah, b0h, b1h);
                MMA_BF16(O[0], pah, b0l, b1l);
                MMA_BF16(O[0], pal, b0h, b1h);
                MMA_BF16(O[1], pah, b2h, b3h);
                MMA_BF16(O[1], pah, b2l, b3l);
                MMA_BF16(O[1], pal, b2h, b3h);
            }
            {
                uint32_t a0h, a0l, a1h, a1l;
                split2(sc[10][0], sc[10][1], a0h, a0l);
                split2(sc[10][2], sc[10][3], a1h, a1l);
                uint32_t vH = VthU + vOff2 + (uint32_t)((n0h + 40) * 4);
                uint32_t b0h, b1h, b0l, b1l;
                LDSM_X2(b0h, b1h, vH);
                LDSM_X2(b0l, b1l, vH + ATT_VWORDS * 4);
                MMA_BF16_K8(O[0], a0h, a1h, b0h);
                MMA_BF16_K8(O[0], a0h, a1h, b0l);
                MMA_BF16_K8(O[0], a0l, a1l, b0h);
                MMA_BF16_K8(O[1], a0h, a1h, b1h);
                MMA_BF16_K8(O[1], a0h, a1h, b1l);
                MMA_BF16_K8(O[1], a0l, a1l, b1h);
            }
        }

        float iA = 1.0f / lA, iB = 1.0f / lB;
        #pragma unroll
        for (int n2 = 0; n2 < 2; n2++) {
            int pidx = head * 8 + n2 * 4 + q;
            uint32_t h, l;
            split2(O[n2][0] * iA, O[n2][1] * iA, h, l);
            g_atth[(tokbase + r0) * EP + pidx] = h;
            g_attl[(tokbase + r0) * EP + pidx] = l;
            if (v1) {
                split2(O[n2][2] * iB, O[n2][3] * iB, h, l);
                g_atth[(tokbase + r1) * EP + pidx] = h;
                g_attl[(tokbase + r1) * EP + pidx] = l;
            }
        }
    }
}

// =================== fused residual-add + LayerNorm (+ split out) ============
__global__ __launch_bounds__(256) void add_ln_kernel(
    const float* hin, const float* __restrict__ delta,
    const float* __restrict__ g, const float* __restrict__ beta,
    float* hout, int wsplit)
{
    int row  = blockIdx.x * 8 + (threadIdx.x >> 5);
    int lane = threadIdx.x & 31;
    size_t base = (size_t)row * kE;

    float4 hv = *reinterpret_cast<const float4*>(&hin  [base + lane * 4]);
    float4 dv = *reinterpret_cast<const float4*>(&delta[base + lane * 4]);
    float v0 = hv.x + dv.x, v1 = hv.y + dv.y, v2 = hv.z + dv.z, v3 = hv.w + dv.w;

    float s = v0 + v1 + v2 + v3;
    #pragma unroll
    for (int o = 16; o; o >>= 1) s += __shfl_xor_sync(0xffffffffu, s, o);
    float mean = s * (1.0f / kE);

    float d0 = v0 - mean, d1 = v1 - mean, d2 = v2 - mean, d3 = v3 - mean;
    float sq = d0 * d0 + d1 * d1 + d2 * d2 + d3 * d3;
    #pragma unroll
    for (int o = 16; o; o >>= 1) sq += __shfl_xor_sync(0xffffffffu, sq, o);
    float rstd = rsqrtf(sq * (1.0f / kE) + 1e-5f);

    float4 gv = *reinterpret_cast<const float4*>(&g   [lane * 4]);
    float4 bv = *reinterpret_cast<const float4*>(&beta[lane * 4]);
    float4 ov;
    ov.x = d0 * rstd * gv.x + bv.x;
    ov.y = d1 * rstd * gv.y + bv.y;
    ov.z = d2 * rstd * gv.z + bv.z;
    ov.w = d3 * rstd * gv.w + bv.w;
    *reinterpret_cast<float4*>(&hout[base + lane * 4]) = ov;

    if (wsplit) {
        uint32_t h0, l0, h1, l1;
        split2(ov.x, ov.y, h0, l0);
        split2(ov.z, ov.w, h1, l1);
        size_t pb = (size_t)row * EP + lane * 2;
        g_hh[pb] = h0;     g_hl[pb] = l0;
        g_hh[pb + 1] = h1; g_hl[pb + 1] = l1;
    }
}

// =================== launch ===================
extern "C" void kernel_launch(void* const* d_in, const int* in_sizes, int n_in,
                              void* d_out, int out_size)
{
    const float* x        = (const float*)d_in[0];
    const int*   t_idx    = (const int*)  d_in[1];
    const int*   sp_idx   = (const int*)  d_in[2];
    const float* conv_w   = (const float*)d_in[3];
    const float* conv_b   = (const float*)d_in[4];
    const float* pos      = (const float*)d_in[5];
    const float* time_tab = (const float*)d_in[6];
    const float* spat_tab = (const float*)d_in[7];
    const float* cls      = (const float*)d_in[8];
    const float* Wqkv     = (const float*)d_in[9];
    const float* bqkv     = (const float*)d_in[10];
    const float* Wo       = (const float*)d_in[11];
    const float* bo       = (const float*)d_in[12];
    const float* W1       = (const float*)d_in[13];
    const float* b1       = (const float*)d_in[14];
    const float* W2       = (const float*)d_in[15];
    const float* b2       = (const float*)d_in[16];
    const float* ln1g     = (const float*)d_in[17];
    const float* ln1b     = (const float*)d_in[18];
    const float* ln2g     = (const float*)d_in[19];
    const float* ln2b     = (const float*)d_in[20];
    float* out = (float*)d_out;

    float *p_h, *p_proj;
    uint32_t *p_hh, *p_hl, *p_qkvh, *p_qkvl, *p_atth, *p_attl, *p_ff1h, *p_ff1l;
    uint32_t *p_wqkvh, *p_wqkvl, *p_woh, *p_wol, *p_w1h, *p_w1l, *p_w2h, *p_w2l;
    cudaGetSymbolAddress((void**)&p_h,     g_h);
    cudaGetSymbolAddress((void**)&p_proj,  g_proj);
    cudaGetSymbolAddress((void**)&p_hh,    g_hh);
    cudaGetSymbolAddress((void**)&p_hl,    g_hl);
    cudaGetSymbolAddress((void**)&p_qkvh,  g_qkvh);
    cudaGetSymbolAddress((void**)&p_qkvl,  g_qkvl);
    cudaGetSymbolAddress((void**)&p_atth,  g_atth);
    cudaGetSymbolAddress((void**)&p_attl,  g_attl);
    cudaGetSymbolAddress((void**)&p_ff1h,  g_ff1h);
    cudaGetSymbolAddress((void**)&p_ff1l,  g_ff1l);
    cudaGetSymbolAddress((void**)&p_wqkvh, g_wqkvh);
    cudaGetSymbolAddress((void**)&p_wqkvl, g_wqkvl);
    cudaGetSymbolAddress((void**)&p_woh,   g_woh);
    cudaGetSymbolAddress((void**)&p_wol,   g_wol);
    cudaGetSymbolAddress((void**)&p_w1h,   g_w1h);
    cudaGetSymbolAddress((void**)&p_w1l,   g_w1l);
    cudaGetSymbolAddress((void**)&p_w2h,   g_w2h);
    cudaGetSymbolAddress((void**)&p_w2l,   g_w2l);

    cudaFuncSetAttribute(gemm_mma_kernel,
        cudaFuncAttributeMaxDynamicSharedMemorySize, GEMM_SMEM_BYTES);
    cudaFuncSetAttribute(attn_mma_kernel,
        cudaFuncAttributeMaxDynamicSharedMemorySize, ATT_SMEM_BYTES);

    // one-time weight splits (single launch)
    wsplit_all_kernel<<<(NW_TOT + 255) / 256, 256>>>(
        Wqkv, Wo, W1, W2,
        p_wqkvh, p_wqkvl, p_woh, p_wol, p_w1h, p_w1l, p_w2h, p_w2l);

    embed_kernel<<<kM, 128>>>(x, t_idx, sp_idx, conv_w, conv_b, pos,
                              time_tab, spat_tab, cls);

    for (int i = 0; i < kLayers; i++) {
        // QKV: [M,128] -> [M,384]  (split output)
        gemm_mma_kernel<<<dim3(384 / BN, kM / BM), 256, GEMM_SMEM_BYTES>>>(
            p_hh, p_hl, p_wqkvh + (size_t)i * 384 * EP, p_wqkvl + (size_t)i * 384 * EP,
            bqkv + (size_t)i * 384, nullptr, p_qkvh, p_qkvl, kM, 384, EP, 1);

        // attention -> att split
        attn_mma_kernel<<<kB * kH, 256, ATT_SMEM_BYTES>>>(p_qkvh, p_qkvl);

        // O-proj: [M,128] -> [M,128]  (fp32 output)
        gemm_mma_kernel<<<dim3(kE / BN, kM / BM), 256, GEMM_SMEM_BYTES>>>(
            p_atth, p_attl, p_woh + (size_t)i * kE * EP, p_wol + (size_t)i * kE * EP,
            bo + (size_t)i * kE, p_proj, nullptr, nullptr, kM, kE, EP, 0);

        // h = LN(h + o), emit split
        add_ln_kernel<<<kM / 8, 256>>>(p_h, p_proj,
            ln1g + (size_t)i * kE, ln1b + (size_t)i * kE, p_h, 1);

        // FFN1 + relu: [M,128] -> [M,512]  (split output)
        gemm_mma_kernel<<<dim3(kFF / BN, kM / BM), 256, GEMM_SMEM_BYTES>>>(
            p_hh, p_hl, p_w1h + (size_t)i * kFF * EP, p_w1l + (size_t)i * kFF * EP,
            b1 + (size_t)i * kFF, nullptr, p_ff1h, p_ff1l, kM, kFF, EP, 2);

        // FFN2: [M,512] -> [M,128]  (fp32 output)
        gemm_mma_kernel<<<dim3(kE / BN, kM / BM), 256, GEMM_SMEM_BYTES>>>(
            p_ff1h, p_ff1l, p_w2h + (size_t)i * kE * FP, p_w2l + (size_t)i * kE * FP,
            b2 + (size_t)i * kE, p_proj, nullptr, nullptr, kM, kE, FP, 0);

        // h = LN(h + ff); last layer writes d_out
        float* dst = (i == kLayers - 1) ? out : p_h;
        add_ln_kernel<<<kM / 8, 256>>>(p_h, p_proj,
            ln2g + (size_t)i * kE, ln2b + (size_t)i * kE, dst,
            (i == kLayers - 1) ? 0 : 1);
    }
}

// round 16
// speedup vs baseline: 1.9408x; 1.4302x over previous
#include <cuda_runtime.h>
#include <cuda_fp16.h>
#include <cstdint>

// ---------------- problem constants ----------------
constexpr int kB      = 128;
constexpr int kSeq    = 252;
constexpr int kWin    = 96;
constexpr int kLeads  = 12;
constexpr int kS      = 264;   // kSeq + kLeads
constexpr int kE      = 128;
constexpr int kH      = 8;
constexpr int kD      = 16;    // kE / kH
constexpr int kFF     = 512;
constexpr int kLayers = 12;
constexpr int kM      = kB * kS;   // 33792 tokens

// pair-widths (K/2) for packed fp16 activations
constexpr int EP  = kE / 2;    // 64
constexpr int QP  = 192;       // 384/2
constexpr int FP  = kFF / 2;   // 256

// ---------------- scratch (device globals; no allocation allowed) ------------
__device__ float g_h   [kM * kE];   // residual stream (fp32)
__device__ float g_proj[kM * kE];   // O-proj / FFN2 fp32 outputs
__device__ uint32_t g_hp  [kM * EP];    // h packed fp16 (QKV/FFN1 input)
__device__ uint32_t g_qkvp[kM * QP];    // qkv packed (attention input)
__device__ uint32_t g_attp[kM * EP];    // attention out (O-proj input)
__device__ uint32_t g_ff1p[kM * FP];    // ff1 out (FFN2 input)
__device__ uint32_t g_wqkvp[kLayers * 384 * EP];
__device__ uint32_t g_wop  [kLayers * kE  * EP];
__device__ uint32_t g_w1p  [kLayers * kFF * EP];
__device__ uint32_t g_w2p  [kLayers * kE  * FP];

// split sizes (pairs)
constexpr int NW_QKV = kLayers * 384 * EP;
constexpr int NW_O   = kLayers * kE  * EP;
constexpr int NW_1   = kLayers * kFF * EP;
constexpr int NW_2   = kLayers * kE  * FP;
constexpr int NW_TOT = NW_QKV + NW_O + NW_1 + NW_2;

// ---------------- fp16 pack helper ----------------
__device__ __forceinline__ uint32_t packhf(float a, float b) {
    __half2 t = __floats2half2_rn(a, b);
    return *reinterpret_cast<uint32_t*>(&t);
}

#define MMA_FP16(d, a, b0, b1)                                                \
    asm volatile("mma.sync.aligned.m16n8k16.row.col.f32.f16.f16.f32 "         \
                 "{%0,%1,%2,%3}, {%4,%5,%6,%7}, {%8,%9}, {%0,%1,%2,%3};"      \
                 : "+f"(d[0]), "+f"(d[1]), "+f"(d[2]), "+f"(d[3])             \
                 : "r"(a[0]), "r"(a[1]), "r"(a[2]), "r"(a[3]),                \
                   "r"(b0), "r"(b1))

#define MMA_FP16_K8(d, a0, a1, b0)                                            \
    asm volatile("mma.sync.aligned.m16n8k8.row.col.f32.f16.f16.f32 "          \
                 "{%0,%1,%2,%3}, {%4,%5}, {%6}, {%0,%1,%2,%3};"               \
                 : "+f"(d[0]), "+f"(d[1]), "+f"(d[2]), "+f"(d[3])             \
                 : "r"(a0), "r"(a1), "r"(b0))

#define LDSM_X4(r0, r1, r2, r3, addr)                                         \
    asm volatile("ldmatrix.sync.aligned.m8n8.x4.shared.b16 {%0,%1,%2,%3}, [%4];" \
                 : "=r"(r0), "=r"(r1), "=r"(r2), "=r"(r3) : "r"(addr))

#define LDSM_X2(r0, r1, addr)                                                 \
    asm volatile("ldmatrix.sync.aligned.m8n8.x2.shared.b16 {%0,%1}, [%2];"    \
                 : "=r"(r0), "=r"(r1) : "r"(addr))

__device__ __forceinline__ void cp16(uint32_t* dst, const uint32_t* src) {
    uint32_t s = (uint32_t)__cvta_generic_to_shared(dst);
    asm volatile("cp.async.ca.shared.global [%0], [%1], 16;" :: "r"(s), "l"(src));
}
__device__ __forceinline__ uint32_t smem_u32(const void* p) {
    uint32_t a;
    asm("{ .reg .u64 t; cvta.to.shared.u64 t, %1; cvt.u32.u64 %0, t; }"
        : "=r"(a) : "l"(p));
    return a;
}

// =================== combined weight pack (one launch) ===================
__global__ __launch_bounds__(256) void wsplit_all_kernel(
    const float* __restrict__ Wqkv, const float* __restrict__ Wo,
    const float* __restrict__ W1,   const float* __restrict__ W2,
    uint32_t* __restrict__ qp, uint32_t* __restrict__ op,
    uint32_t* __restrict__ p1, uint32_t* __restrict__ p2)
{
    int i = blockIdx.x * 256 + threadIdx.x;
    if (i >= NW_TOT) return;
    const float* src;
    uint32_t* dp;
    int j = i;
    if (j < NW_QKV)                       { src = Wqkv; dp = qp; }
    else if ((j -= NW_QKV) < NW_O)        { src = Wo;   dp = op; }
    else if ((j -= NW_O) < NW_1)          { src = W1;   dp = p1; }
    else { j -= NW_1;                       src = W2;   dp = p2; }
    float2 v = *(const float2*)&src[2 * j];
    dp[j] = packhf(v.x, v.y);
}

// =================== embedding (writes fp32 h + pack) ===================
__global__ __launch_bounds__(128) void embed_kernel(
    const float* __restrict__ x, const int* __restrict__ t_idx,
    const int* __restrict__ sp_idx, const float* __restrict__ conv_w,
    const float* __restrict__ conv_b, const float* __restrict__ pos,
    const float* __restrict__ time_tab, const float* __restrict__ spat_tab,
    const float* __restrict__ cls)
{
    int token = blockIdx.x;
    int b = token / kS, s = token % kS;
    int e = threadIdx.x;
    float val;
    if (s < kLeads) {
        val = cls[s * kE + e] + pos[s * kE + e];
    } else {
        int l = s - kLeads;
        __shared__ float xs[kWin];
        if (e < kWin) xs[e] = x[((size_t)b * kSeq + l) * kWin + e];
        __syncthreads();
        float dot = 0.f;
        #pragma unroll 8
        for (int t = 0; t < kWin; t++) dot += xs[t] * conv_w[e * kWin + t];
        int ti = t_idx [b * kSeq + l];
        int si = sp_idx[b * kSeq + l];
        val = dot + conv_b[e] + pos[s * kE + e]
                  + time_tab[ti * kE + e] + spat_tab[si * kE + e];
    }
    g_h[(size_t)token * kE + e] = val;
    float vn = __shfl_down_sync(0xffffffffu, val, 1);
    if (!(e & 1)) {
        g_hp[(size_t)token * EP + (e >> 1)] = packhf(val, vn);
    }
}

// =================== fp16 GEMM, 2-stage cp.async + ldmatrix ==================
// C[M,N] = A[M,2Kp] @ W[N,2Kp]^T + bias, packed fp16 pair operands.
// BM=128 BN=64, BKP=16 pairs (K=32) per iter, 256 thr, warp tile 32x32.
// mode: 0 = fp32 out, 1 = packed fp16 out, 2 = relu + packed out.
constexpr int BM = 128, BN = 64, BKP = 16;
constexpr int PSTR = 20;                  // smem row stride (pairs), pad 4
constexpr int GA = BM * PSTR;             // 2560
constexpr int GW = BN * PSTR;             // 1280
constexpr int GBUF = GA + GW;             // 3840 words per stage
constexpr int GEMM_SMEM_BYTES = 2 * GBUF * 4;   // 30720

__global__ __launch_bounds__(256) void gemm_mma_kernel(
    const uint32_t* __restrict__ Ap, const uint32_t* __restrict__ Wp,
    const float* __restrict__ bias,
    float* __restrict__ Cf, uint32_t* __restrict__ Cp,
    int M, int N, int Kp, int mode)
{
    extern __shared__ uint32_t gsm[];
    uint32_t gsmU = smem_u32(gsm);

    int t = threadIdx.x;
    int bm = blockIdx.y * BM, bn = blockIdx.x * BN;

    // staging mapping
    int saRow = t >> 1;              // 0..127
    int saOfs = (t & 1) * 8;         // 0 or 8
    int swRow = t >> 2;              // 0..63
    int swOfs = (t & 3) * 4;         // 0,4,8,12

    const uint32_t* app = Ap + (size_t)(bm + saRow) * Kp + saOfs;
    const uint32_t* wpp = Wp + (size_t)(bn + swRow) * Kp + swOfs;

    int wid = t >> 5, lane = t & 31;
    int wm = (wid & 3) * 32;
    int wn = (wid >> 2) * 32;
    int grp = lane >> 2, q = lane & 3;

    // ldmatrix per-lane byte offsets (relative to stage-buffer base)
    uint32_t aOff = (uint32_t)(((wm + (lane & 15)) * PSTR + (lane >> 4) * 4) * 4);
    uint32_t wOff = (uint32_t)((GA + (wn + (lane >> 4) * 8 + (lane & 7)) * PSTR
                                + ((lane >> 3) & 1) * 4) * 4);

    float acc[2][4][4] = {};
    int nIter = Kp / BKP;

    // stage 0
    {
        uint32_t* B = gsm;
        cp16(&B[saRow * PSTR + saOfs],         app);
        cp16(&B[saRow * PSTR + saOfs + 4],     app + 4);
        cp16(&B[GA + swRow * PSTR + swOfs],    wpp);
        asm volatile("cp.async.commit_group;");
    }

    for (int it = 0; it < nIter; it++) {
        if (it + 1 < nIter) {
            uint32_t* B = gsm + ((it + 1) & 1) * GBUF;
            int o = (it + 1) * BKP;
            cp16(&B[saRow * PSTR + saOfs],         app + o);
            cp16(&B[saRow * PSTR + saOfs + 4],     app + o + 4);
            cp16(&B[GA + swRow * PSTR + swOfs],    wpp + o);
            asm volatile("cp.async.commit_group;");
            asm volatile("cp.async.wait_group 1;");
        } else {
            asm volatile("cp.async.wait_group 0;");
        }
        __syncthreads();

        uint32_t base = gsmU + (uint32_t)((it & 1) * (GBUF * 4));

        #pragma unroll
        for (int ks = 0; ks < 2; ks++) {
            uint32_t aA = base + aOff + ks * 32;
            uint32_t a0[4], a1[4];
            LDSM_X4(a0[0], a0[1], a0[2], a0[3], aA);
            LDSM_X4(a1[0], a1[1], a1[2], a1[3], aA + 16 * PSTR * 4);

            uint32_t wA = base + wOff + ks * 32;
            uint32_t w[8];
            LDSM_X4(w[0], w[1], w[2], w[3], wA);
            LDSM_X4(w[4], w[5], w[6], w[7], wA + 16 * PSTR * 4);

            #pragma unroll
            for (int nt = 0; nt < 4; nt++) {
                MMA_FP16(acc[0][nt], a0, w[2 * nt], w[2 * nt + 1]);
                MMA_FP16(acc[1][nt], a1, w[2 * nt], w[2 * nt + 1]);
            }
        }
        __syncthreads();
    }

    int Np = N >> 1;
    #pragma unroll
    for (int mt = 0; mt < 2; mt++) {
        int row = bm + wm + mt * 16 + grp;
        #pragma unroll
        for (int nt = 0; nt < 4; nt++) {
            int col = bn + wn + nt * 8 + q * 2;
            float b0 = bias[col], b1 = bias[col + 1];
            float v00 = acc[mt][nt][0] + b0, v01 = acc[mt][nt][1] + b1;
            float v10 = acc[mt][nt][2] + b0, v11 = acc[mt][nt][3] + b1;
            if (mode == 2) {
                v00 = fmaxf(v00, 0.f); v01 = fmaxf(v01, 0.f);
                v10 = fmaxf(v10, 0.f); v11 = fmaxf(v11, 0.f);
            }
            if (mode == 0) {
                float2 o0 = make_float2(v00, v01);
                float2 o1 = make_float2(v10, v11);
                *(float2*)&Cf[(size_t)row * N + col]       = o0;
                *(float2*)&Cf[(size_t)(row + 8) * N + col] = o1;
            } else {
                int pidx = (col >> 1);
                Cp[(size_t)row * Np + pidx]       = packhf(v00, v01);
                Cp[(size_t)(row + 8) * Np + pidx] = packhf(v10, v11);
            }
        }
    }
}

// =================== fp16 flash attention, prepacked qkv, ldmatrix ===========
constexpr int KSTRP = 12;
constexpr int VSTR  = 140;
constexpr int ATT_KWORDS = kS * KSTRP;        // 3168
constexpr int ATT_VWORDS = kD * VSTR;         // 2240
constexpr int ATT_SMEM_BYTES = (ATT_KWORDS + ATT_VWORDS) * 4;  // 21632

__global__ __launch_bounds__(256) void attn_mma_kernel(
    const uint32_t* __restrict__ qkvp)
{
    extern __shared__ uint32_t asm_[];
    uint32_t* Kp  = asm_;
    uint32_t* Vtp = asm_ + ATT_KWORDS;
    uint32_t KpU  = smem_u32(Kp);
    uint32_t VtpU = smem_u32(Vtp);

    int bh = blockIdx.x;
    int b = bh >> 3, head = bh & 7;
    int tid = threadIdx.x;
    const size_t tokbase = (size_t)b * kS;

    for (int i = tid; i < kS * 2; i += 256) {
        int s = i >> 1, c = (i & 1) * 4;
        cp16(&Kp[s * KSTRP + c], qkvp + (tokbase + s) * QP + 64 + head * 8 + c);
    }
    asm volatile("cp.async.commit_group;");
    for (int i = tid; i < 132 * 8; i += 256) {
        int j = i >> 3, pd = i & 7;
        size_t r0 = (tokbase + 2 * j) * QP + 128 + head * 8 + pd;
        size_t r1 = r0 + QP;
        uint32_t w0 = qkvp[r0], w1 = qkvp[r1];
        Vtp[(2 * pd)     * VSTR + j] = __byte_perm(w0, w1, 0x5410);
        Vtp[(2 * pd + 1) * VSTR + j] = __byte_perm(w0, w1, 0x7632);
    }
    asm volatile("cp.async.wait_group 0;");
    __syncthreads();

    int wid = tid >> 5, lane = tid & 31;
    int grp = lane >> 2, q = lane & 3;

    uint32_t kOff  = (uint32_t)((((lane >> 4) * 8 + (lane & 7)) * KSTRP
                                 + ((lane >> 3) & 1) * 4) * 4);
    uint32_t kOff2 = (uint32_t)(((lane & 7) * KSTRP + ((lane >> 3) & 1) * 4) * 4);
    uint32_t vOff  = (uint32_t)((((lane >> 4) * 8 + (lane & 7)) * VSTR
                                 + ((lane >> 3) & 1) * 4) * 4);
    uint32_t vOff2 = (uint32_t)(((lane & 15) * VSTR) * 4);

    for (int mt = wid; mt < 17; mt += 8) {
        int r0 = mt * 16 + grp;
        int r1 = r0 + 8;
        bool v1 = (r1 < kS);

        uint32_t qf[4];
        {
            size_t b0 = (tokbase + r0) * QP + head * 8;
            size_t b1 = (tokbase + (v1 ? r1 : r0)) * QP + head * 8;
            qf[0] = qkvp[b0 + q];
            qf[2] = qkvp[b0 + q + 4];
            qf[1] = v1 ? qkvp[b1 + q]     : 0u;
            qf[3] = v1 ? qkvp[b1 + q + 4] : 0u;
        }

        float mA = -1e30f, mB = -1e30f, lA = 0.f, lB = 0.f;
        float O[2][4] = {};

        for (int ch = 0; ch < 3; ch++) {
            int n0 = ch * 88;
            int n0h = ch * 44;

            // ---- scores S = Q @ K^T ----
            float sc[11][4];
            #pragma unroll
            for (int nt = 0; nt < 11; nt++) {
                sc[nt][0] = 0.f; sc[nt][1] = 0.f; sc[nt][2] = 0.f; sc[nt][3] = 0.f;
            }
            #pragma unroll
            for (int ntp = 0; ntp < 5; ntp++) {
                uint32_t aH = KpU + kOff + (uint32_t)((n0 + ntp * 16) * KSTRP * 4);
                uint32_t b0, b1, b2, b3;
                LDSM_X4(b0, b1, b2, b3, aH);
                MMA_FP16(sc[2*ntp],   qf, b0, b1);
                MMA_FP16(sc[2*ntp+1], qf, b2, b3);
            }
            {
                uint32_t aH = KpU + kOff2 + (uint32_t)((n0 + 80) * KSTRP * 4);
                uint32_t b0, b1;
                LDSM_X2(b0, b1, aH);
                MMA_FP16(sc[10], qf, b0, b1);
            }
            #pragma unroll
            for (int nt = 0; nt < 11; nt++) {
                sc[nt][0] *= 0.25f; sc[nt][1] *= 0.25f;
                sc[nt][2] *= 0.25f; sc[nt][3] *= 0.25f;
            }

            // ---- online softmax ----
            float cmA = -1e30f, cmB = -1e30f;
            #pragma unroll
            for (int nt = 0; nt < 11; nt++) {
                cmA = fmaxf(cmA, fmaxf(sc[nt][0], sc[nt][1]));
                cmB = fmaxf(cmB, fmaxf(sc[nt][2], sc[nt][3]));
            }
            cmA = fmaxf(cmA, __shfl_xor_sync(0xffffffffu, cmA, 1));
            cmA = fmaxf(cmA, __shfl_xor_sync(0xffffffffu, cmA, 2));
            cmB = fmaxf(cmB, __shfl_xor_sync(0xffffffffu, cmB, 1));
            cmB = fmaxf(cmB, __shfl_xor_sync(0xffffffffu, cmB, 2));

            float mnA = fmaxf(mA, cmA), mnB = fmaxf(mB, cmB);
            float aA = __expf(mA - mnA), aB = __expf(mB - mnB);
            mA = mnA; mB = mnB;

            float sA = 0.f, sB = 0.f;
            #pragma unroll
            for (int nt = 0; nt < 11; nt++) {
                sc[nt][0] = __expf(sc[nt][0] - mA);
                sc[nt][1] = __expf(sc[nt][1] - mA);
                sc[nt][2] = __expf(sc[nt][2] - mB);
                sc[nt][3] = __expf(sc[nt][3] - mB);
                sA += sc[nt][0] + sc[nt][1];
                sB += sc[nt][2] + sc[nt][3];
            }
            sA += __shfl_xor_sync(0xffffffffu, sA, 1);
            sA += __shfl_xor_sync(0xffffffffu, sA, 2);
            sB += __shfl_xor_sync(0xffffffffu, sB, 1);
            sB += __shfl_xor_sync(0xffffffffu, sB, 2);
            lA = lA * aA + sA;
            lB = lB * aB + sB;
            #pragma unroll
            for (int n2 = 0; n2 < 2; n2++) {
                O[n2][0] *= aA; O[n2][1] *= aA;
                O[n2][2] *= aB; O[n2][3] *= aB;
            }

            // ---- O += P @ V ----
            #pragma unroll
            for (int kt = 0; kt < 5; kt++) {
                uint32_t pa[4];
                pa[0] = packhf(sc[2*kt][0],   sc[2*kt][1]);
                pa[1] = packhf(sc[2*kt][2],   sc[2*kt][3]);
                pa[2] = packhf(sc[2*kt+1][0], sc[2*kt+1][1]);
                pa[3] = packhf(sc[2*kt+1][2], sc[2*kt+1][3]);
                uint32_t vH = VtpU + vOff + (uint32_t)((n0h + kt * 8) * 4);
                uint32_t b0, b1, b2, b3;
                LDSM_X4(b0, b1, b2, b3, vH);
                MMA_FP16(O[0], pa, b0, b1);
                MMA_FP16(O[1], pa, b2, b3);
            }
            {
                uint32_t a0 = packhf(sc[10][0], sc[10][1]);
                uint32_t a1 = packhf(sc[10][2], sc[10][3]);
                uint32_t vH = VtpU + vOff2 + (uint32_t)((n0h + 40) * 4);
                uint32_t b0, b1;
                LDSM_X2(b0, b1, vH);
                MMA_FP16_K8(O[0], a0, a1, b0);
                MMA_FP16_K8(O[1], a0, a1, b1);
            }
        }

        float iA = 1.0f / lA, iB = 1.0f / lB;
        #pragma unroll
        for (int n2 = 0; n2 < 2; n2++) {
            int pidx = head * 8 + n2 * 4 + q;
            g_attp[(tokbase + r0) * EP + pidx] = packhf(O[n2][0] * iA, O[n2][1] * iA);
            if (v1) {
                g_attp[(tokbase + r1) * EP + pidx] = packhf(O[n2][2] * iB, O[n2][3] * iB);
            }
        }
    }
}

// =================== fused residual-add + LayerNorm (+ pack out) =============
__global__ __launch_bounds__(256) void add_ln_kernel(
    const float* hin, const float* __restrict__ delta,
    const float* __restrict__ g, const float* __restrict__ beta,
    float* hout, int wpack)
{
    int row  = blockIdx.x * 8 + (threadIdx.x >> 5);
    int lane = threadIdx.x & 31;
    size_t base = (size_t)row * kE;

    float4 hv = *reinterpret_cast<const float4*>(&hin  [base + lane * 4]);
    float4 dv = *reinterpret_cast<const float4*>(&delta[base + lane * 4]);
    float v0 = hv.x + dv.x, v1 = hv.y + dv.y, v2 = hv.z + dv.z, v3 = hv.w + dv.w;

    float s = v0 + v1 + v2 + v3;
    #pragma unroll
    for (int o = 16; o; o >>= 1) s += __shfl_xor_sync(0xffffffffu, s, o);
    float mean = s * (1.0f / kE);

    float d0 = v0 - mean, d1 = v1 - mean, d2 = v2 - mean, d3 = v3 - mean;
    float sq = d0 * d0 + d1 * d1 + d2 * d2 + d3 * d3;
    #pragma unroll
    for (int o = 16; o; o >>= 1) sq += __shfl_xor_sync(0xffffffffu, sq, o);
    float rstd = rsqrtf(sq * (1.0f / kE) + 1e-5f);

    float4 gv = *reinterpret_cast<const float4*>(&g   [lane * 4]);
    float4 bv = *reinterpret_cast<const float4*>(&beta[lane * 4]);
    float4 ov;
    ov.x = d0 * rstd * gv.x + bv.x;
    ov.y = d1 * rstd * gv.y + bv.y;
    ov.z = d2 * rstd * gv.z + bv.z;
    ov.w = d3 * rstd * gv.w + bv.w;
    *reinterpret_cast<float4*>(&hout[base + lane * 4]) = ov;

    if (wpack) {
        size_t pb = (size_t)row * EP + lane * 2;
        g_hp[pb]     = packhf(ov.x, ov.y);
        g_hp[pb + 1] = packhf(ov.z, ov.w);
    }
}

// =================== launch ===================
extern "C" void kernel_launch(void* const* d_in, const int* in_sizes, int n_in,
                              void* d_out, int out_size)
{
    const float* x        = (const float*)d_in[0];
    const int*   t_idx    = (const int*)  d_in[1];
    const int*   sp_idx   = (const int*)  d_in[2];
    const float* conv_w   = (const float*)d_in[3];
    const float* conv_b   = (const float*)d_in[4];
    const float* pos      = (const float*)d_in[5];
    const float* time_tab = (const float*)d_in[6];
    const float* spat_tab = (const float*)d_in[7];
    const float* cls      = (const float*)d_in[8];
    const float* Wqkv     = (const float*)d_in[9];
    const float* bqkv     = (const float*)d_in[10];
    const float* Wo       = (const float*)d_in[11];
    const float* bo       = (const float*)d_in[12];
    const float* W1       = (const float*)d_in[13];
    const float* b1       = (const float*)d_in[14];
    const float* W2       = (const float*)d_in[15];
    const float* b2       = (const float*)d_in[16];
    const float* ln1g     = (const float*)d_in[17];
    const float* ln1b     = (const float*)d_in[18];
    const float* ln2g     = (const float*)d_in[19];
    const float* ln2b     = (const float*)d_in[20];
    float* out = (float*)d_out;

    float *p_h, *p_proj;
    uint32_t *p_hp, *p_qkvp, *p_attp, *p_ff1p;
    uint32_t *p_wqkvp, *p_wop, *p_w1p, *p_w2p;
    cudaGetSymbolAddress((void**)&p_h,     g_h);
    cudaGetSymbolAddress((void**)&p_proj,  g_proj);
    cudaGetSymbolAddress((void**)&p_hp,    g_hp);
    cudaGetSymbolAddress((void**)&p_qkvp,  g_qkvp);
    cudaGetSymbolAddress((void**)&p_attp,  g_attp);
    cudaGetSymbolAddress((void**)&p_ff1p,  g_ff1p);
    cudaGetSymbolAddress((void**)&p_wqkvp, g_wqkvp);
    cudaGetSymbolAddress((void**)&p_wop,   g_wop);
    cudaGetSymbolAddress((void**)&p_w1p,   g_w1p);
    cudaGetSymbolAddress((void**)&p_w2p,   g_w2p);

    cudaFuncSetAttribute(gemm_mma_kernel,
        cudaFuncAttributeMaxDynamicSharedMemorySize, GEMM_SMEM_BYTES);
    cudaFuncSetAttribute(attn_mma_kernel,
        cudaFuncAttributeMaxDynamicSharedMemorySize, ATT_SMEM_BYTES);

    // one-time weight packing (single launch)
    wsplit_all_kernel<<<(NW_TOT + 255) / 256, 256>>>(
        Wqkv, Wo, W1, W2, p_wqkvp, p_wop, p_w1p, p_w2p);

    embed_kernel<<<kM, 128>>>(x, t_idx, sp_idx, conv_w, conv_b, pos,
                              time_tab, spat_tab, cls);

    for (int i = 0; i < kLayers; i++) {
        // QKV: [M,128] -> [M,384]  (packed output)
        gemm_mma_kernel<<<dim3(384 / BN, kM / BM), 256, GEMM_SMEM_BYTES>>>(
            p_hp, p_wqkvp + (size_t)i * 384 * EP,
            bqkv + (size_t)i * 384, nullptr, p_qkvp, kM, 384, EP, 1);

        // attention -> packed
        attn_mma_kernel<<<kB * kH, 256, ATT_SMEM_BYTES>>>(p_qkvp);

        // O-proj: [M,128] -> [M,128]  (fp32 output)
        gemm_mma_kernel<<<dim3(kE / BN, kM / BM), 256, GEMM_SMEM_BYTES>>>(
            p_attp, p_wop + (size_t)i * kE * EP,
            bo + (size_t)i * kE, p_proj, nullptr, kM, kE, EP, 0);

        // h = LN(h + o), emit pack
        add_ln_kernel<<<kM / 8, 256>>>(p_h, p_proj,
            ln1g + (size_t)i * kE, ln1b + (size_t)i * kE, p_h, 1);

        // FFN1 + relu: [M,128] -> [M,512]  (packed output)
        gemm_mma_kernel<<<dim3(kFF / BN, kM / BM), 256, GEMM_SMEM_BYTES>>>(
            p_hp, p_w1p + (size_t)i * kFF * EP,
            b1 + (size_t)i * kFF, nullptr, p_ff1p, kM, kFF, EP, 2);

        // FFN2: [M,512] -> [M,128]  (fp32 output)
        gemm_mma_kernel<<<dim3(kE / BN, kM / BM), 256, GEMM_SMEM_BYTES>>>(
            p_ff1p, p_w2p + (size_t)i * kE * FP,
            b2 + (size_t)i * kE, p_proj, nullptr, kM, kE, FP, 0);

        // h = LN(h + ff); last layer writes d_out
        float* dst = (i == kLayers - 1) ? out : p_h;
        add_ln_kernel<<<kM / 8, 256>>>(p_h, p_proj,
            ln2g + (size_t)i * kE, ln2b + (size_t)i * kE, dst,
            (i == kLayers - 1) ? 0 : 1);
    }
}

// round 17
// speedup vs baseline: 2.0307x; 1.0463x over previous
#include <cuda_runtime.h>
#include <cuda_fp16.h>
#include <cstdint>

// ---------------- problem constants ----------------
constexpr int kB      = 128;
constexpr int kSeq    = 252;
constexpr int kWin    = 96;
constexpr int kLeads  = 12;
constexpr int kS      = 264;   // kSeq + kLeads
constexpr int kE      = 128;
constexpr int kH      = 8;
constexpr int kD      = 16;    // kE / kH
constexpr int kFF     = 512;
constexpr int kLayers = 12;
constexpr int kM      = kB * kS;   // 33792 tokens

// pair-widths (K/2) for packed fp16 activations
constexpr int EP  = kE / 2;    // 64
constexpr int QP  = 192;       // 384/2
constexpr int FP  = kFF / 2;   // 256

// ---------------- scratch (device globals; no allocation allowed) ------------
__device__ float g_h   [kM * kE];   // residual stream (fp32)
__device__ float g_proj[kM * kE];   // O-proj / FFN2 fp32 outputs
__device__ uint32_t g_hp  [kM * EP];    // h packed fp16 (QKV/FFN1 input)
__device__ uint32_t g_qkvp[kM * QP];    // qkv packed (attention input)
__device__ uint32_t g_attp[kM * EP];    // attention out (O-proj input)
__device__ uint32_t g_ff1p[kM * FP];    // ff1 out (FFN2 input)
__device__ uint32_t g_wqkvp[kLayers * 384 * EP];
__device__ uint32_t g_wop  [kLayers * kE  * EP];
__device__ uint32_t g_w1p  [kLayers * kFF * EP];
__device__ uint32_t g_w2p  [kLayers * kE  * FP];

// split sizes (pairs)
constexpr int NW_QKV = kLayers * 384 * EP;
constexpr int NW_O   = kLayers * kE  * EP;
constexpr int NW_1   = kLayers * kFF * EP;
constexpr int NW_2   = kLayers * kE  * FP;
constexpr int NW_TOT = NW_QKV + NW_O + NW_1 + NW_2;

// ---------------- fp16 pack helper ----------------
__device__ __forceinline__ uint32_t packhf(float a, float b) {
    __half2 t = __floats2half2_rn(a, b);
    return *reinterpret_cast<uint32_t*>(&t);
}

#define MMA_FP16(d, a, b0, b1)                                                \
    asm volatile("mma.sync.aligned.m16n8k16.row.col.f32.f16.f16.f32 "         \
                 "{%0,%1,%2,%3}, {%4,%5,%6,%7}, {%8,%9}, {%0,%1,%2,%3};"      \
                 : "+f"(d[0]), "+f"(d[1]), "+f"(d[2]), "+f"(d[3])             \
                 : "r"(a[0]), "r"(a[1]), "r"(a[2]), "r"(a[3]),                \
                   "r"(b0), "r"(b1))

#define MMA_FP16_K8(d, a0, a1, b0)                                            \
    asm volatile("mma.sync.aligned.m16n8k8.row.col.f32.f16.f16.f32 "          \
                 "{%0,%1,%2,%3}, {%4,%5}, {%6}, {%0,%1,%2,%3};"               \
                 : "+f"(d[0]), "+f"(d[1]), "+f"(d[2]), "+f"(d[3])             \
                 : "r"(a0), "r"(a1), "r"(b0))

#define LDSM_X4(r0, r1, r2, r3, addr)                                         \
    asm volatile("ldmatrix.sync.aligned.m8n8.x4.shared.b16 {%0,%1,%2,%3}, [%4];" \
                 : "=r"(r0), "=r"(r1), "=r"(r2), "=r"(r3) : "r"(addr))

#define LDSM_X2(r0, r1, addr)                                                 \
    asm volatile("ldmatrix.sync.aligned.m8n8.x2.shared.b16 {%0,%1}, [%2];"    \
                 : "=r"(r0), "=r"(r1) : "r"(addr))

__device__ __forceinline__ void cp16(uint32_t* dst, const uint32_t* src) {
    uint32_t s = (uint32_t)__cvta_generic_to_shared(dst);
    asm volatile("cp.async.ca.shared.global [%0], [%1], 16;" :: "r"(s), "l"(src));
}
__device__ __forceinline__ uint32_t smem_u32(const void* p) {
    uint32_t a;
    asm("{ .reg .u64 t; cvta.to.shared.u64 t, %1; cvt.u32.u64 %0, t; }"
        : "=r"(a) : "l"(p));
    return a;
}

// =================== combined weight pack (one launch) ===================
__global__ __launch_bounds__(256) void wsplit_all_kernel(
    const float* __restrict__ Wqkv, const float* __restrict__ Wo,
    const float* __restrict__ W1,   const float* __restrict__ W2,
    uint32_t* __restrict__ qp, uint32_t* __restrict__ op,
    uint32_t* __restrict__ p1, uint32_t* __restrict__ p2)
{
    int i = blockIdx.x * 256 + threadIdx.x;
    if (i >= NW_TOT) return;
    const float* src;
    uint32_t* dp;
    int j = i;
    if (j < NW_QKV)                       { src = Wqkv; dp = qp; }
    else if ((j -= NW_QKV) < NW_O)        { src = Wo;   dp = op; }
    else if ((j -= NW_O) < NW_1)          { src = W1;   dp = p1; }
    else { j -= NW_1;                       src = W2;   dp = p2; }
    float2 v = *(const float2*)&src[2 * j];
    dp[j] = packhf(v.x, v.y);
}

// =================== embedding (writes fp32 h + pack) ===================
__global__ __launch_bounds__(128) void embed_kernel(
    const float* __restrict__ x, const int* __restrict__ t_idx,
    const int* __restrict__ sp_idx, const float* __restrict__ conv_w,
    const float* __restrict__ conv_b, const float* __restrict__ pos,
    const float* __restrict__ time_tab, const float* __restrict__ spat_tab,
    const float* __restrict__ cls)
{
    int token = blockIdx.x;
    int b = token / kS, s = token % kS;
    int e = threadIdx.x;
    float val;
    if (s < kLeads) {
        val = cls[s * kE + e] + pos[s * kE + e];
    } else {
        int l = s - kLeads;
        __shared__ float xs[kWin];
        if (e < kWin) xs[e] = x[((size_t)b * kSeq + l) * kWin + e];
        __syncthreads();
        float dot = 0.f;
        #pragma unroll 8
        for (int t = 0; t < kWin; t++) dot += xs[t] * conv_w[e * kWin + t];
        int ti = t_idx [b * kSeq + l];
        int si = sp_idx[b * kSeq + l];
        val = dot + conv_b[e] + pos[s * kE + e]
                  + time_tab[ti * kE + e] + spat_tab[si * kE + e];
    }
    g_h[(size_t)token * kE + e] = val;
    float vn = __shfl_down_sync(0xffffffffu, val, 1);
    if (!(e & 1)) {
        g_hp[(size_t)token * EP + (e >> 1)] = packhf(val, vn);
    }
}

// =================== fp16 GEMM, 2-stage cp.async + ldmatrix ==================
// C[M,N] = A[M,2Kp] @ W[N,2Kp]^T + bias, packed fp16 pair operands.
// BM=128 BN=64, BKP=16 pairs (K=32) per iter, 256 thr, warp tile 32x32.
// __launch_bounds__(256,3): cap regs at 85 -> 3 CTAs/SM (smem 30KBx3 fits).
// mode: 0 = fp32 out, 1 = packed fp16 out, 2 = relu + packed out.
constexpr int BM = 128, BN = 64, BKP = 16;
constexpr int PSTR = 20;                  // smem row stride (pairs), pad 4
constexpr int GA = BM * PSTR;             // 2560
constexpr int GW = BN * PSTR;             // 1280
constexpr int GBUF = GA + GW;             // 3840 words per stage
constexpr int GEMM_SMEM_BYTES = 2 * GBUF * 4;   // 30720

__global__ __launch_bounds__(256, 3) void gemm_mma_kernel(
    const uint32_t* __restrict__ Ap, const uint32_t* __restrict__ Wp,
    const float* __restrict__ bias,
    float* __restrict__ Cf, uint32_t* __restrict__ Cp,
    int M, int N, int Kp, int mode)
{
    extern __shared__ uint32_t gsm[];
    uint32_t gsmU = smem_u32(gsm);

    int t = threadIdx.x;
    int bm = blockIdx.y * BM, bn = blockIdx.x * BN;

    // staging mapping
    int saRow = t >> 1;              // 0..127
    int saOfs = (t & 1) * 8;         // 0 or 8
    int swRow = t >> 2;              // 0..63
    int swOfs = (t & 3) * 4;         // 0,4,8,12

    const uint32_t* app = Ap + (size_t)(bm + saRow) * Kp + saOfs;
    const uint32_t* wpp = Wp + (size_t)(bn + swRow) * Kp + swOfs;

    int wid = t >> 5, lane = t & 31;
    int wm = (wid & 3) * 32;
    int wn = (wid >> 2) * 32;
    int grp = lane >> 2, q = lane & 3;

    // ldmatrix per-lane byte offsets (relative to stage-buffer base)
    uint32_t aOff = (uint32_t)(((wm + (lane & 15)) * PSTR + (lane >> 4) * 4) * 4);
    uint32_t wOff = (uint32_t)((GA + (wn + (lane >> 4) * 8 + (lane & 7)) * PSTR
                                + ((lane >> 3) & 1) * 4) * 4);

    float acc[2][4][4] = {};
    int nIter = Kp / BKP;

    // stage 0
    {
        uint32_t* B = gsm;
        cp16(&B[saRow * PSTR + saOfs],         app);
        cp16(&B[saRow * PSTR + saOfs + 4],     app + 4);
        cp16(&B[GA + swRow * PSTR + swOfs],    wpp);
        asm volatile("cp.async.commit_group;");
    }

    for (int it = 0; it < nIter; it++) {
        if (it + 1 < nIter) {
            uint32_t* B = gsm + ((it + 1) & 1) * GBUF;
            int o = (it + 1) * BKP;
            cp16(&B[saRow * PSTR + saOfs],         app + o);
            cp16(&B[saRow * PSTR + saOfs + 4],     app + o + 4);
            cp16(&B[GA + swRow * PSTR + swOfs],    wpp + o);
            asm volatile("cp.async.commit_group;");
            asm volatile("cp.async.wait_group 1;");
        } else {
            asm volatile("cp.async.wait_group 0;");
        }
        __syncthreads();

        uint32_t base = gsmU + (uint32_t)((it & 1) * (GBUF * 4));

        #pragma unroll
        for (int ks = 0; ks < 2; ks++) {
            uint32_t aA = base + aOff + ks * 32;
            uint32_t a0[4], a1[4];
            LDSM_X4(a0[0], a0[1], a0[2], a0[3], aA);
            LDSM_X4(a1[0], a1[1], a1[2], a1[3], aA + 16 * PSTR * 4);

            uint32_t wA = base + wOff + ks * 32;
            uint32_t w[8];
            LDSM_X4(w[0], w[1], w[2], w[3], wA);
            LDSM_X4(w[4], w[5], w[6], w[7], wA + 16 * PSTR * 4);

            #pragma unroll
            for (int nt = 0; nt < 4; nt++) {
                MMA_FP16(acc[0][nt], a0, w[2 * nt], w[2 * nt + 1]);
                MMA_FP16(acc[1][nt], a1, w[2 * nt], w[2 * nt + 1]);
            }
        }
        __syncthreads();
    }

    int Np = N >> 1;
    #pragma unroll
    for (int mt = 0; mt < 2; mt++) {
        int row = bm + wm + mt * 16 + grp;
        #pragma unroll
        for (int nt = 0; nt < 4; nt++) {
            int col = bn + wn + nt * 8 + q * 2;
            float b0 = bias[col], b1 = bias[col + 1];
            float v00 = acc[mt][nt][0] + b0, v01 = acc[mt][nt][1] + b1;
            float v10 = acc[mt][nt][2] + b0, v11 = acc[mt][nt][3] + b1;
            if (mode == 2) {
                v00 = fmaxf(v00, 0.f); v01 = fmaxf(v01, 0.f);
                v10 = fmaxf(v10, 0.f); v11 = fmaxf(v11, 0.f);
            }
            if (mode == 0) {
                float2 o0 = make_float2(v00, v01);
                float2 o1 = make_float2(v10, v11);
                *(float2*)&Cf[(size_t)row * N + col]       = o0;
                *(float2*)&Cf[(size_t)(row + 8) * N + col] = o1;
            } else {
                int pidx = (col >> 1);
                Cp[(size_t)row * Np + pidx]       = packhf(v00, v01);
                Cp[(size_t)(row + 8) * Np + pidx] = packhf(v10, v11);
            }
        }
    }
}

// =================== fp16 flash attention, prepacked qkv, ldmatrix ===========
constexpr int KSTRP = 12;
constexpr int VSTR  = 140;
constexpr int ATT_KWORDS = kS * KSTRP;        // 3168
constexpr int ATT_VWORDS = kD * VSTR;         // 2240
constexpr int ATT_SMEM_BYTES = (ATT_KWORDS + ATT_VWORDS) * 4;  // 21632

__global__ __launch_bounds__(256, 3) void attn_mma_kernel(
    const uint32_t* __restrict__ qkvp)
{
    extern __shared__ uint32_t asm_[];
    uint32_t* Kp  = asm_;
    uint32_t* Vtp = asm_ + ATT_KWORDS;
    uint32_t KpU  = smem_u32(Kp);
    uint32_t VtpU = smem_u32(Vtp);

    int bh = blockIdx.x;
    int b = bh >> 3, head = bh & 7;
    int tid = threadIdx.x;
    const size_t tokbase = (size_t)b * kS;

    for (int i = tid; i < kS * 2; i += 256) {
        int s = i >> 1, c = (i & 1) * 4;
        cp16(&Kp[s * KSTRP + c], qkvp + (tokbase + s) * QP + 64 + head * 8 + c);
    }
    asm volatile("cp.async.commit_group;");
    for (int i = tid; i < 132 * 8; i += 256) {
        int j = i >> 3, pd = i & 7;
        size_t r0 = (tokbase + 2 * j) * QP + 128 + head * 8 + pd;
        size_t r1 = r0 + QP;
        uint32_t w0 = qkvp[r0], w1 = qkvp[r1];
        Vtp[(2 * pd)     * VSTR + j] = __byte_perm(w0, w1, 0x5410);
        Vtp[(2 * pd + 1) * VSTR + j] = __byte_perm(w0, w1, 0x7632);
    }
    asm volatile("cp.async.wait_group 0;");
    __syncthreads();

    int wid = tid >> 5, lane = tid & 31;
    int grp = lane >> 2, q = lane & 3;

    uint32_t kOff  = (uint32_t)((((lane >> 4) * 8 + (lane & 7)) * KSTRP
                                 + ((lane >> 3) & 1) * 4) * 4);
    uint32_t kOff2 = (uint32_t)(((lane & 7) * KSTRP + ((lane >> 3) & 1) * 4) * 4);
    uint32_t vOff  = (uint32_t)((((lane >> 4) * 8 + (lane & 7)) * VSTR
                                 + ((lane >> 3) & 1) * 4) * 4);
    uint32_t vOff2 = (uint32_t)(((lane & 15) * VSTR) * 4);

    for (int mt = wid; mt < 17; mt += 8) {
        int r0 = mt * 16 + grp;
        int r1 = r0 + 8;
        bool v1 = (r1 < kS);

        uint32_t qf[4];
        {
            size_t b0 = (tokbase + r0) * QP + head * 8;
            size_t b1 = (tokbase + (v1 ? r1 : r0)) * QP + head * 8;
            qf[0] = qkvp[b0 + q];
            qf[2] = qkvp[b0 + q + 4];
            qf[1] = v1 ? qkvp[b1 + q]     : 0u;
            qf[3] = v1 ? qkvp[b1 + q + 4] : 0u;
        }

        float mA = -1e30f, mB = -1e30f, lA = 0.f, lB = 0.f;
        float O[2][4] = {};

        for (int ch = 0; ch < 3; ch++) {
            int n0 = ch * 88;
            int n0h = ch * 44;

            // ---- scores S = Q @ K^T ----
            float sc[11][4];
            #pragma unroll
            for (int nt = 0; nt < 11; nt++) {
                sc[nt][0] = 0.f; sc[nt][1] = 0.f; sc[nt][2] = 0.f; sc[nt][3] = 0.f;
            }
            #pragma unroll
            for (int ntp = 0; ntp < 5; ntp++) {
                uint32_t aH = KpU + kOff + (uint32_t)((n0 + ntp * 16) * KSTRP * 4);
                uint32_t b0, b1, b2, b3;
                LDSM_X4(b0, b1, b2, b3, aH);
                MMA_FP16(sc[2*ntp],   qf, b0, b1);
                MMA_FP16(sc[2*ntp+1], qf, b2, b3);
            }
            {
                uint32_t aH = KpU + kOff2 + (uint32_t)((n0 + 80) * KSTRP * 4);
                uint32_t b0, b1;
                LDSM_X2(b0, b1, aH);
                MMA_FP16(sc[10], qf, b0, b1);
            }
            #pragma unroll
            for (int nt = 0; nt < 11; nt++) {
                sc[nt][0] *= 0.25f; sc[nt][1] *= 0.25f;
                sc[nt][2] *= 0.25f; sc[nt][3] *= 0.25f;
            }

            // ---- online softmax ----
            float cmA = -1e30f, cmB = -1e30f;
            #pragma unroll
            for (int nt = 0; nt < 11; nt++) {
                cmA = fmaxf(cmA, fmaxf(sc[nt][0], sc[nt][1]));
                cmB = fmaxf(cmB, fmaxf(sc[nt][2], sc[nt][3]));
            }
            cmA = fmaxf(cmA, __shfl_xor_sync(0xffffffffu, cmA, 1));
            cmA = fmaxf(cmA, __shfl_xor_sync(0xffffffffu, cmA, 2));
            cmB = fmaxf(cmB, __shfl_xor_sync(0xffffffffu, cmB, 1));
            cmB = fmaxf(cmB, __shfl_xor_sync(0xffffffffu, cmB, 2));

            float mnA = fmaxf(mA, cmA), mnB = fmaxf(mB, cmB);
            float aA = __expf(mA - mnA), aB = __expf(mB - mnB);
            mA = mnA; mB = mnB;

            float sA = 0.f, sB = 0.f;
            #pragma unroll
            for (int nt = 0; nt < 11; nt++) {
                sc[nt][0] = __expf(sc[nt][0] - mA);
                sc[nt][1] = __expf(sc[nt][1] - mA);
                sc[nt][2] = __expf(sc[nt][2] - mB);
                sc[nt][3] = __expf(sc[nt][3] - mB);
                sA += sc[nt][0] + sc[nt][1];
                sB += sc[nt][2] + sc[nt][3];
            }
            sA += __shfl_xor_sync(0xffffffffu, sA, 1);
            sA += __shfl_xor_sync(0xffffffffu, sA, 2);
            sB += __shfl_xor_sync(0xffffffffu, sB, 1);
            sB += __shfl_xor_sync(0xffffffffu, sB, 2);
            lA = lA * aA + sA;
            lB = lB * aB + sB;
            #pragma unroll
            for (int n2 = 0; n2 < 2; n2++) {
                O[n2][0] *= aA; O[n2][1] *= aA;
                O[n2][2] *= aB; O[n2][3] *= aB;
            }

            // ---- O += P @ V ----
            #pragma unroll
            for (int kt = 0; kt < 5; kt++) {
                uint32_t pa[4];
                pa[0] = packhf(sc[2*kt][0],   sc[2*kt][1]);
                pa[1] = packhf(sc[2*kt][2],   sc[2*kt][3]);
                pa[2] = packhf(sc[2*kt+1][0], sc[2*kt+1][1]);
                pa[3] = packhf(sc[2*kt+1][2], sc[2*kt+1][3]);
                uint32_t vH = VtpU + vOff + (uint32_t)((n0h + kt * 8) * 4);
                uint32_t b0, b1, b2, b3;
                LDSM_X4(b0, b1, b2, b3, vH);
                MMA_FP16(O[0], pa, b0, b1);
                MMA_FP16(O[1], pa, b2, b3);
            }
            {
                uint32_t a0 = packhf(sc[10][0], sc[10][1]);
                uint32_t a1 = packhf(sc[10][2], sc[10][3]);
                uint32_t vH = VtpU + vOff2 + (uint32_t)((n0h + 40) * 4);
                uint32_t b0, b1;
                LDSM_X2(b0, b1, vH);
                MMA_FP16_K8(O[0], a0, a1, b0);
                MMA_FP16_K8(O[1], a0, a1, b1);
            }
        }

        float iA = 1.0f / lA, iB = 1.0f / lB;
        #pragma unroll
        for (int n2 = 0; n2 < 2; n2++) {
            int pidx = head * 8 + n2 * 4 + q;
            g_attp[(tokbase + r0) * EP + pidx] = packhf(O[n2][0] * iA, O[n2][1] * iA);
            if (v1) {
                g_attp[(tokbase + r1) * EP + pidx] = packhf(O[n2][2] * iB, O[n2][3] * iB);
            }
        }
    }
}

// =================== fused residual-add + LayerNorm (+ pack out) =============
__global__ __launch_bounds__(256) void add_ln_kernel(
    const float* hin, const float* __restrict__ delta,
    const float* __restrict__ g, const float* __restrict__ beta,
    float* hout, int wpack)
{
    int row  = blockIdx.x * 8 + (threadIdx.x >> 5);
    int lane = threadIdx.x & 31;
    size_t base = (size_t)row * kE;

    float4 hv = *reinterpret_cast<const float4*>(&hin  [base + lane * 4]);
    float4 dv = *reinterpret_cast<const float4*>(&delta[base + lane * 4]);
    float v0 = hv.x + dv.x, v1 = hv.y + dv.y, v2 = hv.z + dv.z, v3 = hv.w + dv.w;

    float s = v0 + v1 + v2 + v3;
    #pragma unroll
    for (int o = 16; o; o >>= 1) s += __shfl_xor_sync(0xffffffffu, s, o);
    float mean = s * (1.0f / kE);

    float d0 = v0 - mean, d1 = v1 - mean, d2 = v2 - mean, d3 = v3 - mean;
    float sq = d0 * d0 + d1 * d1 + d2 * d2 + d3 * d3;
    #pragma unroll
    for (int o = 16; o; o >>= 1) sq += __shfl_xor_sync(0xffffffffu, sq, o);
    float rstd = rsqrtf(sq * (1.0f / kE) + 1e-5f);

    float4 gv = *reinterpret_cast<const float4*>(&g   [lane * 4]);
    float4 bv = *reinterpret_cast<const float4*>(&beta[lane * 4]);
    float4 ov;
    ov.x = d0 * rstd * gv.x + bv.x;
    ov.y = d1 * rstd * gv.y + bv.y;
    ov.z = d2 * rstd * gv.z + bv.z;
    ov.w = d3 * rstd * gv.w + bv.w;
    *reinterpret_cast<float4*>(&hout[base + lane * 4]) = ov;

    if (wpack) {
        size_t pb = (size_t)row * EP + lane * 2;
        g_hp[pb]     = packhf(ov.x, ov.y);
        g_hp[pb + 1] = packhf(ov.z, ov.w);
    }
}

// =================== launch ===================
extern "C" void kernel_launch(void* const* d_in, const int* in_sizes, int n_in,
                              void* d_out, int out_size)
{
    const float* x        = (const float*)d_in[0];
    const int*   t_idx    = (const int*)  d_in[1];
    const int*   sp_idx   = (const int*)  d_in[2];
    const float* conv_w   = (const float*)d_in[3];
    const float* conv_b   = (const float*)d_in[4];
    const float* pos      = (const float*)d_in[5];
    const float* time_tab = (const float*)d_in[6];
    const float* spat_tab = (const float*)d_in[7];
    const float* cls      = (const float*)d_in[8];
    const float* Wqkv     = (const float*)d_in[9];
    const float* bqkv     = (const float*)d_in[10];
    const float* Wo       = (const float*)d_in[11];
    const float* bo       = (const float*)d_in[12];
    const float* W1       = (const float*)d_in[13];
    const float* b1       = (const float*)d_in[14];
    const float* W2       = (const float*)d_in[15];
    const float* b2       = (const float*)d_in[16];
    const float* ln1g     = (const float*)d_in[17];
    const float* ln1b     = (const float*)d_in[18];
    const float* ln2g     = (const float*)d_in[19];
    const float* ln2b     = (const float*)d_in[20];
    float* out = (float*)d_out;

    float *p_h, *p_proj;
    uint32_t *p_hp, *p_qkvp, *p_attp, *p_ff1p;
    uint32_t *p_wqkvp, *p_wop, *p_w1p, *p_w2p;
    cudaGetSymbolAddress((void**)&p_h,     g_h);
    cudaGetSymbolAddress((void**)&p_proj,  g_proj);
    cudaGetSymbolAddress((void**)&p_hp,    g_hp);
    cudaGetSymbolAddress((void**)&p_qkvp,  g_qkvp);
    cudaGetSymbolAddress((void**)&p_attp,  g_attp);
    cudaGetSymbolAddress((void**)&p_ff1p,  g_ff1p);
    cudaGetSymbolAddress((void**)&p_wqkvp, g_wqkvp);
    cudaGetSymbolAddress((void**)&p_wop,   g_wop);
    cudaGetSymbolAddress((void**)&p_w1p,   g_w1p);
    cudaGetSymbolAddress((void**)&p_w2p,   g_w2p);

    cudaFuncSetAttribute(gemm_mma_kernel,
        cudaFuncAttributeMaxDynamicSharedMemorySize, GEMM_SMEM_BYTES);
    cudaFuncSetAttribute(attn_mma_kernel,
        cudaFuncAttributeMaxDynamicSharedMemorySize, ATT_SMEM_BYTES);

    // one-time weight packing (single launch)
    wsplit_all_kernel<<<(NW_TOT + 255) / 256, 256>>>(
        Wqkv, Wo, W1, W2, p_wqkvp, p_wop, p_w1p, p_w2p);

    embed_kernel<<<kM, 128>>>(x, t_idx, sp_idx, conv_w, conv_b, pos,
                              time_tab, spat_tab, cls);

    for (int i = 0; i < kLayers; i++) {
        // QKV: [M,128] -> [M,384]  (packed output)
        gemm_mma_kernel<<<dim3(384 / BN, kM / BM), 256, GEMM_SMEM_BYTES>>>(
            p_hp, p_wqkvp + (size_t)i * 384 * EP,
            bqkv + (size_t)i * 384, nullptr, p_qkvp, kM, 384, EP, 1);

        // attention -> packed
        attn_mma_kernel<<<kB * kH, 256, ATT_SMEM_BYTES>>>(p_qkvp);

        // O-proj: [M,128] -> [M,128]  (fp32 output)
        gemm_mma_kernel<<<dim3(kE / BN, kM / BM), 256, GEMM_SMEM_BYTES>>>(
            p_attp, p_wop + (size_t)i * kE * EP,
            bo + (size_t)i * kE, p_proj, nullptr, kM, kE, EP, 0);

        // h = LN(h + o), emit pack
        add_ln_kernel<<<kM / 8, 256>>>(p_h, p_proj,
            ln1g + (size_t)i * kE, ln1b + (size_t)i * kE, p_h, 1);

        // FFN1 + relu: [M,128] -> [M,512]  (packed output)
        gemm_mma_kernel<<<dim3(kFF / BN, kM / BM), 256, GEMM_SMEM_BYTES>>>(
            p_hp, p_w1p + (size_t)i * kFF * EP,
            b1 + (size_t)i * kFF, nullptr, p_ff1p, kM, kFF, EP, 2);

        // FFN2: [M,512] -> [M,128]  (fp32 output)
        gemm_mma_kernel<<<dim3(kE / BN, kM / BM), 256, GEMM_SMEM_BYTES>>>(
            p_ff1p, p_w2p + (size_t)i * kE * FP,
            b2 + (size_t)i * kE, p_proj, nullptr, kM, kE, FP, 0);

        // h = LN(h + ff); last layer writes d_out
        float* dst = (i == kLayers - 1) ? out : p_h;
        add_ln_kernel<<<kM / 8, 256>>>(p_h, p_proj,
            ln2g + (size_t)i * kE, ln2b + (size_t)i * kE, dst,
            (i == kLayers - 1) ? 0 : 1);
    }
}